// round 2
// baseline (speedup 1.0000x reference)
#include <cuda_runtime.h>
#include <math.h>

#define NB    8
#define NSEQ  1024
#define HIDD  768
#define NH    12
#define LR    256
#define HD    64

typedef unsigned long long u64;

// ---- packed fp32x2 helpers (Blackwell FFMA2 path) -------------------------
__device__ __forceinline__ u64 pk2(float lo, float hi) {
    u64 r; asm("mov.b64 %0, {%1, %2};" : "=l"(r) : "f"(lo), "f"(hi)); return r;
}
__device__ __forceinline__ u64 dup2(float v) {
    u64 r; asm("mov.b64 %0, {%1, %1};" : "=l"(r) : "f"(v)); return r;
}
__device__ __forceinline__ u64 ffma2(u64 a, u64 b, u64 c) {
    u64 d; asm("fma.rn.f32x2 %0, %1, %2, %3;" : "=l"(d) : "l"(a), "l"(b), "l"(c));
    return d;
}
__device__ __forceinline__ u64 fmul2(u64 a, u64 b) {
    u64 d; asm("mul.rn.f32x2 %0, %1, %2;" : "=l"(d) : "l"(a), "l"(b));
    return d;
}
__device__ __forceinline__ float2 up2(u64 v) {
    float2 f; asm("mov.b64 {%0, %1}, %2;" : "=f"(f.x), "=f"(f.y) : "l"(v));
    return f;
}

// Scratch (no cudaMalloc allowed)
__device__ float g_Wc[NH * HD * HIDD];      // [h][e][d]  combined LoRA weight: Wa @ Wt
__device__ float g_t[NB * NH * NSEQ * HD];  // [b][h][n][e] projected tokens (q=k=v)

// ---------------------------------------------------------------------------
// Kernel 1: Wc[h][e][d] = sum_l Wa[h][e][l] * Wt[h][l][d]
// ---------------------------------------------------------------------------
__global__ __launch_bounds__(256) void k_wc(const float* __restrict__ Wt,
                                            const float* __restrict__ Wa) {
    const int h  = blockIdx.x;
    const int d0 = blockIdx.y * 128;
    __shared__ float Wa_s[64 * 36];    // [e][l] pad 36
    __shared__ float Wt_s[32 * 132];   // [l][d] pad 132

    const int tid = threadIdx.x;
    const int te = tid / 16;           // 16 groups of 4 e-rows
    const int td = tid % 16;           // 16 groups of 8 d-cols

    u64 acc[4][4];                     // [i][jp] pairs over 8 d-cols
#pragma unroll
    for (int i = 0; i < 4; i++)
#pragma unroll
        for (int j = 0; j < 4; j++) acc[i][j] = 0ull;

    for (int l0 = 0; l0 < LR; l0 += 32) {
#pragma unroll
        for (int it = 0; it < 2; it++) {
            int f = tid + it * 256;
            int e = f / 8, l4 = f % 8;
            float4 v = *(const float4*)&Wa[((size_t)h * 64 + e) * LR + l0 + l4 * 4];
            *(float4*)&Wa_s[e * 36 + l4 * 4] = v;
        }
#pragma unroll
        for (int it = 0; it < 4; it++) {
            int f = tid + it * 256;
            int l = f / 32, d4 = f % 32;
            float4 v = *(const float4*)&Wt[((size_t)h * LR + l0 + l) * HIDD + d0 + d4 * 4];
            *(float4*)&Wt_s[l * 132 + d4 * 4] = v;
        }
        __syncthreads();
#pragma unroll
        for (int l = 0; l < 32; l++) {
            float4 w0 = *(const float4*)&Wt_s[l * 132 + td * 8];
            float4 w1 = *(const float4*)&Wt_s[l * 132 + td * 8 + 4];
            u64 wp[4] = { pk2(w0.x, w0.y), pk2(w0.z, w0.w),
                          pk2(w1.x, w1.y), pk2(w1.z, w1.w) };
#pragma unroll
            for (int i = 0; i < 4; i++) {
                u64 a = dup2(Wa_s[(te * 4 + i) * 36 + l]);
#pragma unroll
                for (int j = 0; j < 4; j++) acc[i][j] = ffma2(wp[j], a, acc[i][j]);
            }
        }
        __syncthreads();
    }
#pragma unroll
    for (int i = 0; i < 4; i++) {
        float2 a0 = up2(acc[i][0]), a1 = up2(acc[i][1]);
        float2 a2 = up2(acc[i][2]), a3 = up2(acc[i][3]);
        size_t base = ((size_t)h * HD + te * 4 + i) * HIDD + d0 + td * 8;
        *(float4*)&g_Wc[base]     = make_float4(a0.x, a0.y, a1.x, a1.y);
        *(float4*)&g_Wc[base + 4] = make_float4(a2.x, a2.y, a3.x, a3.y);
    }
}

// ---------------------------------------------------------------------------
// Kernel 2: t[b,h,n,e] = sum_d X[b,n,d] * Wc[h,e,d]
// ---------------------------------------------------------------------------
__global__ __launch_bounds__(256) void k_proj(const float* __restrict__ X) {
    const int bh = blockIdx.y;
    const int b = bh / NH, h = bh % NH;
    const int n0 = blockIdx.x * 128;

    __shared__ float Xs[128 * 36];   // [r][k] pad 36
    __shared__ float Ws[32 * 68];    // [k][e] transposed, pad 68

    const int tid = threadIdx.x;
    const int trow = tid / 16;   // 16 groups of 8 rows
    const int tcol = tid % 16;   // 16 groups of 4 cols (e)

    u64 acc[8][2];               // [i][jp] pairs over 4 e-cols
#pragma unroll
    for (int i = 0; i < 8; i++) { acc[i][0] = 0ull; acc[i][1] = 0ull; }

    const float* Xbase = X + ((size_t)b * NSEQ + n0) * HIDD;
    const float* Wbase = g_Wc + (size_t)h * HD * HIDD;

    for (int k0 = 0; k0 < HIDD; k0 += 32) {
#pragma unroll
        for (int it = 0; it < 4; it++) {
            int f = tid + it * 256;
            int r = f / 8, k4 = f % 8;
            float4 v = *(const float4*)&Xbase[(size_t)r * HIDD + k0 + k4 * 4];
            *(float4*)&Xs[r * 36 + k4 * 4] = v;
        }
#pragma unroll
        for (int it = 0; it < 2; it++) {
            int f = tid + it * 256;
            int e = f / 8, k4 = f % 8;
            float4 v = *(const float4*)&Wbase[(size_t)e * HIDD + k0 + k4 * 4];
            Ws[(k4 * 4 + 0) * 68 + e] = v.x;
            Ws[(k4 * 4 + 1) * 68 + e] = v.y;
            Ws[(k4 * 4 + 2) * 68 + e] = v.z;
            Ws[(k4 * 4 + 3) * 68 + e] = v.w;
        }
        __syncthreads();
#pragma unroll
        for (int kk = 0; kk < 32; kk++) {
            float4 wv = *(const float4*)&Ws[kk * 68 + tcol * 4];
            u64 w01 = pk2(wv.x, wv.y);
            u64 w23 = pk2(wv.z, wv.w);
#pragma unroll
            for (int i = 0; i < 8; i++) {
                u64 xd = dup2(Xs[(trow * 8 + i) * 36 + kk]);
                acc[i][0] = ffma2(w01, xd, acc[i][0]);
                acc[i][1] = ffma2(w23, xd, acc[i][1]);
            }
        }
        __syncthreads();
    }
#pragma unroll
    for (int i = 0; i < 8; i++) {
        float2 a0 = up2(acc[i][0]), a1 = up2(acc[i][1]);
        *(float4*)&g_t[((size_t)bh * NSEQ + n0 + trow * 8 + i) * HD + tcol * 4] =
            make_float4(a0.x, a0.y, a1.x, a1.y);
    }
}

// ---------------------------------------------------------------------------
// Kernel 3: flash attention per (b,h). Q=K=V=t[b,h] [1024,64].
// ---------------------------------------------------------------------------
__global__ __launch_bounds__(256) void k_attn(const int* __restrict__ amask,
                                              float* __restrict__ out) {
    extern __shared__ float sm[];
    float* Qs = sm;               // 64*64
    float* Ks = Qs + 64 * 64;     // 64*68
    float* Ps = Ks + 64 * 68;     // 64*64
    int*   mk = (int*)(Ps + 64 * 64);  // 64

    const int bh = blockIdx.y;
    const int b = bh / NH, h = bh % NH;
    const int q0 = blockIdx.x * 64;
    const int tid = threadIdx.x;
    const int trow = tid / 16;
    const int tcol = tid % 16;

    const float* T = g_t + (size_t)bh * NSEQ * HD;
    const float scale = 0.03608439182435161f;  // 768^-0.5

#pragma unroll
    for (int it = 0; it < 4; it++) {
        int f = tid + it * 256;
        int r = f / 16, e4 = f % 16;
        float4 v = *(const float4*)&T[(size_t)(q0 + r) * HD + e4 * 4];
        v.x *= scale; v.y *= scale; v.z *= scale; v.w *= scale;
        *(float4*)&Qs[r * 64 + e4 * 4] = v;
    }

    float m[4], l[4];
    u64 o2[4][2];                 // packed output acc: cols tcol*4+{0,1},{2,3}
#pragma unroll
    for (int i = 0; i < 4; i++) {
        m[i] = -1e30f; l[i] = 0.f;
        o2[i][0] = 0ull; o2[i][1] = 0ull;
    }

    const int* maskb = amask + (size_t)b * NSEQ;

    for (int j0 = 0; j0 < NSEQ; j0 += 64) {
#pragma unroll
        for (int it = 0; it < 4; it++) {
            int f = tid + it * 256;
            int r = f / 16, e4 = f % 16;
            *(float4*)&Ks[r * 68 + e4 * 4] =
                *(const float4*)&T[(size_t)(j0 + r) * HD + e4 * 4];
        }
        if (tid < 64) mk[tid] = maskb[j0 + tid];
        __syncthreads();

        // S tile packed: s2[i][jp] = (col tcol+16*(2jp), col tcol+16*(2jp+1))
        u64 s2[4][2];
#pragma unroll
        for (int i = 0; i < 4; i++) { s2[i][0] = 0ull; s2[i][1] = 0ull; }

#pragma unroll
        for (int e4 = 0; e4 < 16; e4++) {
            float4 kv[4];
#pragma unroll
            for (int j = 0; j < 4; j++)
                kv[j] = *(const float4*)&Ks[(tcol + 16 * j) * 68 + e4 * 4];
            u64 kp[2][4];
            kp[0][0] = pk2(kv[0].x, kv[1].x); kp[0][1] = pk2(kv[0].y, kv[1].y);
            kp[0][2] = pk2(kv[0].z, kv[1].z); kp[0][3] = pk2(kv[0].w, kv[1].w);
            kp[1][0] = pk2(kv[2].x, kv[3].x); kp[1][1] = pk2(kv[2].y, kv[3].y);
            kp[1][2] = pk2(kv[2].z, kv[3].z); kp[1][3] = pk2(kv[2].w, kv[3].w);
#pragma unroll
            for (int i = 0; i < 4; i++) {
                float4 qv = *(const float4*)&Qs[(trow * 4 + i) * 64 + e4 * 4];
                u64 qx = dup2(qv.x), qy = dup2(qv.y), qz = dup2(qv.z), qw = dup2(qv.w);
#pragma unroll
                for (int jp = 0; jp < 2; jp++) {
                    s2[i][jp] = ffma2(kp[jp][0], qx, s2[i][jp]);
                    s2[i][jp] = ffma2(kp[jp][1], qy, s2[i][jp]);
                    s2[i][jp] = ffma2(kp[jp][2], qz, s2[i][jp]);
                    s2[i][jp] = ffma2(kp[jp][3], qw, s2[i][jp]);
                }
            }
        }

        // unpack scores
        float s[4][4];
#pragma unroll
        for (int i = 0; i < 4; i++) {
            float2 f0 = up2(s2[i][0]), f1 = up2(s2[i][1]);
            s[i][0] = f0.x; s[i][1] = f0.y; s[i][2] = f1.x; s[i][3] = f1.y;
        }

        // mask (key dim)
#pragma unroll
        for (int j = 0; j < 4; j++) {
            if (mk[tcol + 16 * j] == 0) {
#pragma unroll
                for (int i = 0; i < 4; i++) s[i][j] = -1e30f;
            }
        }

        // row max across the 16 lanes sharing trow
        float mt[4];
#pragma unroll
        for (int i = 0; i < 4; i++) {
            mt[i] = s[i][0];
#pragma unroll
            for (int j = 1; j < 4; j++) mt[i] = fmaxf(mt[i], s[i][j]);
        }
#pragma unroll
        for (int off = 1; off < 16; off <<= 1) {
#pragma unroll
            for (int i = 0; i < 4; i++)
                mt[i] = fmaxf(mt[i], __shfl_xor_sync(0xffffffffu, mt[i], off));
        }

#pragma unroll
        for (int i = 0; i < 4; i++) {
            float mn = fmaxf(m[i], mt[i]);
            float alpha = __expf(m[i] - mn);
            m[i] = mn;
            l[i] *= alpha;
            u64 ad = dup2(alpha);
            o2[i][0] = fmul2(o2[i][0], ad);
            o2[i][1] = fmul2(o2[i][1], ad);
        }

        float ls[4];
#pragma unroll
        for (int i = 0; i < 4; i++) {
            ls[i] = 0.f;
#pragma unroll
            for (int j = 0; j < 4; j++) {
                float p = __expf(s[i][j] - m[i]);
                s[i][j] = p;
                ls[i] += p;
            }
        }
#pragma unroll
        for (int off = 1; off < 16; off <<= 1) {
#pragma unroll
            for (int i = 0; i < 4; i++)
                ls[i] += __shfl_xor_sync(0xffffffffu, ls[i], off);
        }
#pragma unroll
        for (int i = 0; i < 4; i++) l[i] += ls[i];

        // stage P to smem
#pragma unroll
        for (int i = 0; i < 4; i++)
#pragma unroll
            for (int j = 0; j < 4; j++)
                Ps[(trow * 4 + i) * 64 + tcol + 16 * j] = s[i][j];
        __syncthreads();

        // PV: out cols e = tcol*4 .. +3 (packed pairs)
#pragma unroll 4
        for (int jj = 0; jj < 64; jj++) {
            float4 v = *(const float4*)&Ks[jj * 68 + tcol * 4];
            u64 v01 = pk2(v.x, v.y);
            u64 v23 = pk2(v.z, v.w);
#pragma unroll
            for (int i = 0; i < 4; i++) {
                u64 pd = dup2(Ps[(trow * 4 + i) * 64 + jj]);
                o2[i][0] = ffma2(v01, pd, o2[i][0]);
                o2[i][1] = ffma2(v23, pd, o2[i][1]);
            }
        }
        __syncthreads();
    }

    // epilogue: normalize + write out[b][n][h*64+e]
#pragma unroll
    for (int i = 0; i < 4; i++) {
        u64 inv = dup2(1.f / l[i]);
        float2 a0 = up2(fmul2(o2[i][0], inv));
        float2 a1 = up2(fmul2(o2[i][1], inv));
        int n = q0 + trow * 4 + i;
        *(float4*)&out[((size_t)b * NSEQ + n) * (NH * HD) + h * HD + tcol * 4] =
            make_float4(a0.x, a0.y, a1.x, a1.y);
    }
}

// ---------------------------------------------------------------------------
extern "C" void kernel_launch(void* const* d_in, const int* in_sizes, int n_in,
                              void* d_out, int out_size) {
    const float* hidden = (const float*)d_in[0];
    const int*   amask  = (const int*)d_in[1];
    const float* Wt     = (const float*)d_in[2];
    const float* Wa     = (const float*)d_in[3];
    float* out = (float*)d_out;

    k_wc<<<dim3(NH, HIDD / 128), 256>>>(Wt, Wa);
    k_proj<<<dim3(NSEQ / 128, NB * NH), 256>>>(hidden);

    size_t smem = (size_t)(64 * 64 + 64 * 68 + 64 * 64) * sizeof(float)
                + 64 * sizeof(int);
    cudaFuncSetAttribute(k_attn, cudaFuncAttributeMaxDynamicSharedMemorySize,
                         (int)smem);
    k_attn<<<dim3(NSEQ / 64, NB * NH), 256, smem>>>(amask, out);
}

// round 4
// speedup vs baseline: 2.0682x; 2.0682x over previous
#include <cuda_runtime.h>
#include <cstdint>

#define NB    8
#define NSEQ  1024
#define HIDD  768
#define NH    12
#define LR    256
#define HD    64

#define QT    128
#define KT    64
#define NIT   (NSEQ / KT)

// scratch (no cudaMalloc allowed)
__device__ float g_Wc[NH * HD * HIDD];       // [h][e][d]
__device__ float g_t [NB * NH * NSEQ * HD];  // [bh][n][e]  (q=k=v)

// ---------------------------------------------------------------------------
// helpers
// ---------------------------------------------------------------------------
__device__ __forceinline__ uint32_t smem_u32(const void* p) {
    uint32_t a;
    asm("{ .reg .u64 t; cvta.to.shared.u64 t, %1; cvt.u32.u64 %0, t; }"
        : "=r"(a) : "l"(p));
    return a;
}
__device__ __forceinline__ uint32_t cvt_tf32(float f) {
    uint32_t u; asm("cvt.rna.tf32.f32 %0, %1;" : "=r"(u) : "f"(f)); return u;
}
__device__ __forceinline__ uint32_t fbits(float f) { return __float_as_uint(f); }

// m16n8k8 tf32 MMA, accumulate in place
__device__ __forceinline__ void mma8(float* c, const uint32_t* a, const uint32_t* b) {
    asm volatile(
        "mma.sync.aligned.m16n8k8.row.col.f32.tf32.tf32.f32 "
        "{%0,%1,%2,%3}, {%4,%5,%6,%7}, {%8,%9}, {%0,%1,%2,%3};"
        : "+f"(c[0]), "+f"(c[1]), "+f"(c[2]), "+f"(c[3])
        : "r"(a[0]), "r"(a[1]), "r"(a[2]), "r"(a[3]), "r"(b[0]), "r"(b[1]));
}

// fast exp2 on fma/alu pipes (no MUFU); valid for x <= ~30, clamps below -100
__device__ __forceinline__ float fexp2(float x) {
    x = fmaxf(x, -100.0f);
    float t = x + 12582912.0f;            // rint magic (1.5 * 2^23)
    float f = x - (t - 12582912.0f);      // f in [-0.5, 0.5]
    int   sc = __float_as_int(t) << 23;
    float p = 0.0013333558f;
    p = fmaf(p, f, 0.0096181291f);
    p = fmaf(p, f, 0.0555041087f);
    p = fmaf(p, f, 0.2402265069f);
    p = fmaf(p, f, 0.6931471806f);
    p = fmaf(p, f, 1.0f);
    return __int_as_float(__float_as_int(p) + sc);
}

// ---------------------------------------------------------------------------
// Kernel 1: Wc[h][e][d] = sum_l Wa[h][e][l] * Wt[h][l][d]   (fp32 exact)
// ---------------------------------------------------------------------------
__global__ __launch_bounds__(256) void k_wc(const float* __restrict__ Wt,
                                            const float* __restrict__ Wa) {
    const int h  = blockIdx.x;
    const int d0 = blockIdx.y * 128;
    __shared__ float Wa_s[64 * 36];
    __shared__ float Wt_s[32 * 132];

    const int tid = threadIdx.x;
    const int te = tid / 16;
    const int td = tid % 16;

    float acc[4][8];
#pragma unroll
    for (int i = 0; i < 4; i++)
#pragma unroll
        for (int j = 0; j < 8; j++) acc[i][j] = 0.f;

    for (int l0 = 0; l0 < LR; l0 += 32) {
#pragma unroll
        for (int it = 0; it < 2; it++) {
            int f = tid + it * 256;
            int e = f / 8, l4 = f % 8;
            float4 v = *(const float4*)&Wa[((size_t)h * 64 + e) * LR + l0 + l4 * 4];
            *(float4*)&Wa_s[e * 36 + l4 * 4] = v;
        }
#pragma unroll
        for (int it = 0; it < 4; it++) {
            int f = tid + it * 256;
            int l = f / 32, d4 = f % 32;
            float4 v = *(const float4*)&Wt[((size_t)h * LR + l0 + l) * HIDD + d0 + d4 * 4];
            *(float4*)&Wt_s[l * 132 + d4 * 4] = v;
        }
        __syncthreads();
#pragma unroll
        for (int l = 0; l < 32; l++) {
            float a[4];
#pragma unroll
            for (int i = 0; i < 4; i++) a[i] = Wa_s[(te * 4 + i) * 36 + l];
            float w[8];
            *(float4*)&w[0] = *(const float4*)&Wt_s[l * 132 + td * 8];
            *(float4*)&w[4] = *(const float4*)&Wt_s[l * 132 + td * 8 + 4];
#pragma unroll
            for (int i = 0; i < 4; i++)
#pragma unroll
                for (int j = 0; j < 8; j++) acc[i][j] = fmaf(a[i], w[j], acc[i][j]);
        }
        __syncthreads();
    }
#pragma unroll
    for (int i = 0; i < 4; i++) {
        size_t base = ((size_t)h * HD + te * 4 + i) * HIDD + d0 + td * 8;
        *(float4*)&g_Wc[base]     = make_float4(acc[i][0], acc[i][1], acc[i][2], acc[i][3]);
        *(float4*)&g_Wc[base + 4] = make_float4(acc[i][4], acc[i][5], acc[i][6], acc[i][7]);
    }
}

// ---------------------------------------------------------------------------
// Kernel 2: t[bh][n][e] = sum_d X[b,n,d] * Wc[h,e,d]  (fp32 exact)
// ---------------------------------------------------------------------------
__global__ __launch_bounds__(256) void k_proj(const float* __restrict__ X) {
    const int bh = blockIdx.y;
    const int b = bh / NH, h = bh % NH;
    const int n0 = blockIdx.x * 128;

    __shared__ float Xs[128 * 36];
    __shared__ float Ws[32 * 68];

    const int tid = threadIdx.x;
    const int trow = tid / 16;
    const int tcol = tid % 16;

    float acc[8][4];
#pragma unroll
    for (int i = 0; i < 8; i++)
#pragma unroll
        for (int j = 0; j < 4; j++) acc[i][j] = 0.f;

    const float* Xbase = X + ((size_t)b * NSEQ + n0) * HIDD;
    const float* Wbase = g_Wc + (size_t)h * HD * HIDD;

    for (int k0 = 0; k0 < HIDD; k0 += 32) {
#pragma unroll
        for (int it = 0; it < 4; it++) {
            int f = tid + it * 256;
            int r = f / 8, k4 = f % 8;
            float4 v = *(const float4*)&Xbase[(size_t)r * HIDD + k0 + k4 * 4];
            *(float4*)&Xs[r * 36 + k4 * 4] = v;
        }
#pragma unroll
        for (int it = 0; it < 2; it++) {
            int f = tid + it * 256;
            int e = f / 8, k4 = f % 8;
            float4 v = *(const float4*)&Wbase[(size_t)e * HIDD + k0 + k4 * 4];
            Ws[(k4 * 4 + 0) * 68 + e] = v.x;
            Ws[(k4 * 4 + 1) * 68 + e] = v.y;
            Ws[(k4 * 4 + 2) * 68 + e] = v.z;
            Ws[(k4 * 4 + 3) * 68 + e] = v.w;
        }
        __syncthreads();
#pragma unroll
        for (int kk = 0; kk < 32; kk++) {
            float w[4];
            *(float4*)w = *(const float4*)&Ws[kk * 68 + tcol * 4];
            float x[8];
#pragma unroll
            for (int i = 0; i < 8; i++) x[i] = Xs[(trow * 8 + i) * 36 + kk];
#pragma unroll
            for (int i = 0; i < 8; i++)
#pragma unroll
                for (int j = 0; j < 4; j++) acc[i][j] = fmaf(x[i], w[j], acc[i][j]);
        }
        __syncthreads();
    }
#pragma unroll
    for (int i = 0; i < 8; i++) {
        *(float4*)&g_t[((size_t)bh * NSEQ + n0 + trow * 8 + i) * HD + tcol * 4] =
            make_float4(acc[i][0], acc[i][1], acc[i][2], acc[i][3]);
    }
}

// ---------------------------------------------------------------------------
// Kernel 3: tf32 mma.sync flash attention, static-bias softmax.
// CTA = 128 q rows of one (b,h); 8 warps tile 128x64 as 4m x 2n of 32x32.
// One K tile [64 keys x 64 e] serves as B for both Q*K^T and P*V.
// ---------------------------------------------------------------------------
// smem float offsets
#define OF_Q   0                       // 128*68
#define OF_K0  8704                    // 64*68
#define OF_K1  13056                   // 64*68
#define OF_P   17408                   // 128*68
#define OF_B   26112                   // 2*64 bias
#define OF_L   26240                   // 2*128 row-sum halves
#define ATT_SMEM_BYTES (26496 * 4)

#define QSCALE 0.05205654442f          // 768^-0.5 * log2(e)
#define SBIAS  (-12.0f)

__device__ __forceinline__ void issue_tile(uint32_t dstb, const float* src, int tid) {
#pragma unroll
    for (int it = 0; it < 4; it++) {
        int f = tid + it * 256;
        int r = f >> 4, c4 = f & 15;
        uint32_t dst = dstb + (uint32_t)(r * 68 + c4 * 4) * 4u;
        asm volatile("cp.async.cg.shared.global [%0], [%1], 16;"
                     :: "r"(dst), "l"(src + (size_t)r * HD + c4 * 4));
    }
    asm volatile("cp.async.commit_group;" ::: "memory");
}

__global__ __launch_bounds__(256, 2) void k_attn3(const int* __restrict__ amask,
                                                  float* __restrict__ out) {
    extern __shared__ float sm[];
    float* Qs   = sm + OF_Q;
    float* Ps   = sm + OF_P;
    float* lred = sm + OF_L;
    const uint32_t smb = smem_u32(sm);

    const int bh = blockIdx.y, b = bh / NH, h = bh % NH;
    const int q0 = blockIdx.x * QT;
    const int tid = threadIdx.x, wid = tid >> 5, lid = tid & 31;
    const int mw = wid & 3, nw = wid >> 2;
    const int g = lid >> 2, t4 = lid & 3;
    const int mrow = mw * 32, ncol = nw * 32;

    const float* Tq = g_t + (size_t)bh * NSEQ * HD;
    const int*   mb = amask + (size_t)b * NSEQ;

    // prefetch K tile 0 + bias 0
    issue_tile(smb + OF_K0 * 4, Tq, tid);
    if (tid < 64) sm[OF_B + tid] = (mb[tid] == 0) ? -3000.f : SBIAS;

    // load Q (scale + cvt.rna.tf32)
#pragma unroll
    for (int it = 0; it < 8; it++) {
        int f = tid + it * 256;
        int r = f >> 4, c4 = f & 15;
        float4 v = *(const float4*)&Tq[(size_t)(q0 + r) * HD + c4 * 4];
        float4 w;
        w.x = __uint_as_float(cvt_tf32(v.x * QSCALE));
        w.y = __uint_as_float(cvt_tf32(v.y * QSCALE));
        w.z = __uint_as_float(cvt_tf32(v.z * QSCALE));
        w.w = __uint_as_float(cvt_tf32(v.w * QSCALE));
        *(float4*)&Qs[r * 68 + c4 * 4] = w;
    }

    float rs[4] = {0.f, 0.f, 0.f, 0.f};
    float oacc[2][4][4];
#pragma unroll
    for (int mi = 0; mi < 2; mi++)
#pragma unroll
        for (int nj = 0; nj < 4; nj++)
#pragma unroll
            for (int r = 0; r < 4; r++) oacc[mi][nj][r] = 0.f;

    for (int i = 0; i < NIT; i++) {
        asm volatile("cp.async.wait_group 0;" ::: "memory");
        __syncthreads();
        if (i + 1 < NIT) {
            issue_tile(smb + (((i + 1) & 1) ? OF_K1 : OF_K0) * 4,
                       Tq + (size_t)(i + 1) * KT * HD, tid);
            if (tid < 64)
                sm[OF_B + ((i + 1) & 1) * 64 + tid] =
                    (mb[(i + 1) * KT + tid] == 0) ? -3000.f : SBIAS;
        }
        const float* Kc   = sm + ((i & 1) ? OF_K1 : OF_K0);
        const float* bias = sm + OF_B + (i & 1) * 64;

        // ---- S = Q * K^T (this warp: 32x32) ----
        float sacc[2][4][4];
#pragma unroll
        for (int mi = 0; mi < 2; mi++)
#pragma unroll
            for (int nj = 0; nj < 4; nj++)
#pragma unroll
                for (int r = 0; r < 4; r++) sacc[mi][nj][r] = 0.f;

#pragma unroll
        for (int k8 = 0; k8 < 8; k8++) {
            uint32_t a[2][4];
#pragma unroll
            for (int mi = 0; mi < 2; mi++) {
                const float* qp = Qs + (mrow + mi * 16 + g) * 68 + k8 * 8 + t4;
                a[mi][0] = fbits(qp[0]);
                a[mi][1] = fbits(qp[8 * 68]);
                a[mi][2] = fbits(qp[4]);
                a[mi][3] = fbits(qp[8 * 68 + 4]);
            }
#pragma unroll
            for (int nj = 0; nj < 4; nj++) {
                const float* kp = Kc + (ncol + nj * 8 + g) * 68 + k8 * 8 + t4;
                uint32_t bf[2] = { fbits(kp[0]), fbits(kp[4]) };
                mma8(sacc[0][nj], a[0], bf);
                mma8(sacc[1][nj], a[1], bf);
            }
        }

        // ---- softmax (static bias, base-2) + stage P ----
#pragma unroll
        for (int mi = 0; mi < 2; mi++)
#pragma unroll
            for (int nj = 0; nj < 4; nj++) {
                float2 bv = *(const float2*)&bias[nj * 8 + t4 * 2];
                uint32_t u0 = cvt_tf32(fexp2(sacc[mi][nj][0] + bv.x));
                uint32_t u1 = cvt_tf32(fexp2(sacc[mi][nj][1] + bv.y));
                uint32_t u2 = cvt_tf32(fexp2(sacc[mi][nj][2] + bv.x));
                uint32_t u3 = cvt_tf32(fexp2(sacc[mi][nj][3] + bv.y));
                rs[mi * 2 + 0] += __uint_as_float(u0) + __uint_as_float(u1);
                rs[mi * 2 + 1] += __uint_as_float(u2) + __uint_as_float(u3);
                float* pp = Ps + (mrow + mi * 16 + g) * 68 + ncol + nj * 8 + t4 * 2;
                *(float2*)pp = make_float2(__uint_as_float(u0), __uint_as_float(u1));
                *(float2*)(pp + 8 * 68) =
                    make_float2(__uint_as_float(u2), __uint_as_float(u3));
            }
        __syncthreads();

        // ---- O += P * V  (V tile == K tile; B-frags via transposed indexing) ----
#pragma unroll
        for (int k8 = 0; k8 < 8; k8++) {
            uint32_t a[2][4];
#pragma unroll
            for (int mi = 0; mi < 2; mi++) {
                const float* pp = Ps + (mrow + mi * 16 + g) * 68 + k8 * 8 + t4;
                a[mi][0] = fbits(pp[0]);
                a[mi][1] = fbits(pp[8 * 68]);
                a[mi][2] = fbits(pp[4]);
                a[mi][3] = fbits(pp[8 * 68 + 4]);
            }
#pragma unroll
            for (int nj = 0; nj < 4; nj++) {
                const float* vp = Kc + (k8 * 8 + t4) * 68 + ncol + nj * 8 + g;
                uint32_t bf[2] = { fbits(vp[0]), fbits(vp[4 * 68]) };
                mma8(oacc[0][nj], a[0], bf);
                mma8(oacc[1][nj], a[1], bf);
            }
        }
    }

    // ---- epilogue: row sums across quad lanes + warp halves ----
#pragma unroll
    for (int r = 0; r < 4; r++) {
        rs[r] += __shfl_xor_sync(0xffffffffu, rs[r], 1);
        rs[r] += __shfl_xor_sync(0xffffffffu, rs[r], 2);
    }
    if (t4 == 0) {
#pragma unroll
        for (int r = 0; r < 4; r++)
            lred[nw * 128 + mrow + (r >> 1) * 16 + (r & 1) * 8 + g] = rs[r];
    }
    __syncthreads();

#pragma unroll
    for (int mi = 0; mi < 2; mi++) {
        int r0 = mrow + mi * 16 + g;
        float inv0 = 1.f / (lred[r0] + lred[128 + r0]);
        float inv1 = 1.f / (lred[r0 + 8] + lred[128 + r0 + 8]);
        float* ob0 = out + ((size_t)b * NSEQ + q0 + r0) * (NH * HD) + h * HD + ncol;
        float* ob1 = ob0 + (size_t)8 * (NH * HD);
#pragma unroll
        for (int nj = 0; nj < 4; nj++) {
            *(float2*)&ob0[nj * 8 + t4 * 2] =
                make_float2(oacc[mi][nj][0] * inv0, oacc[mi][nj][1] * inv0);
            *(float2*)&ob1[nj * 8 + t4 * 2] =
                make_float2(oacc[mi][nj][2] * inv1, oacc[mi][nj][3] * inv1);
        }
    }
}

// ---------------------------------------------------------------------------
extern "C" void kernel_launch(void* const* d_in, const int* in_sizes, int n_in,
                              void* d_out, int out_size) {
    const float* hidden = (const float*)d_in[0];
    const int*   amask  = (const int*)d_in[1];
    const float* Wt     = (const float*)d_in[2];
    const float* Wa     = (const float*)d_in[3];
    float* out = (float*)d_out;

    k_wc<<<dim3(NH, HIDD / 128), 256>>>(Wt, Wa);
    k_proj<<<dim3(NSEQ / 128, NB * NH), 256>>>(hidden);

    cudaFuncSetAttribute(k_attn3, cudaFuncAttributeMaxDynamicSharedMemorySize,
                         ATT_SMEM_BYTES);
    k_attn3<<<dim3(NSEQ / QT, NB * NH), 256, ATT_SMEM_BYTES>>>(amask, out);
}

// round 5
// speedup vs baseline: 2.7982x; 1.3530x over previous
#include <cuda_runtime.h>
#include <cuda_bf16.h>
#include <cstdint>

#define NB    8
#define NSEQ  1024
#define HIDD  768
#define NH    12
#define LR    256
#define HD    64

#define QT    128
#define KT    64
#define NIT   (NSEQ / KT)

// scratch (no cudaMalloc allowed)
__device__ float    g_t [NB * NH * NSEQ * HD];      // [bh][n][e]  (q=k=v), fp32
__device__ uint32_t g_Xh[NB * NSEQ * (HIDD / 2)];   // bf16 hi, k-pair packed
__device__ uint32_t g_Xl[NB * NSEQ * (HIDD / 2)];   // bf16 lo
__device__ uint32_t g_Wh[NH * HD * (HIDD / 2)];     // Wc bf16 hi, k-pair packed
__device__ uint32_t g_Wl[NH * HD * (HIDD / 2)];     // Wc bf16 lo

// ---------------------------------------------------------------------------
// helpers
// ---------------------------------------------------------------------------
__device__ __forceinline__ uint32_t smem_u32(const void* p) {
    uint32_t a;
    asm("{ .reg .u64 t; cvta.to.shared.u64 t, %1; cvt.u32.u64 %0, t; }"
        : "=r"(a) : "l"(p));
    return a;
}
__device__ __forceinline__ uint32_t cvt_tf32(float f) {
    uint32_t u; asm("cvt.rna.tf32.f32 %0, %1;" : "=r"(u) : "f"(f)); return u;
}
__device__ __forceinline__ uint32_t fbits(float f) { return __float_as_uint(f); }

// pack two floats to bf16x2: low half = 'lo' (even k), high half = 'hi' (odd k)
__device__ __forceinline__ uint32_t packbf(float lo, float hi) {
    uint32_t r;
    asm("cvt.rn.bf16x2.f32 %0, %1, %2;" : "=r"(r) : "f"(hi), "f"(lo));
    return r;
}
// split a float pair into (hi-pack, lo-pack)
__device__ __forceinline__ void split2(float x0, float x1,
                                       uint32_t& hp, uint32_t& lp) {
    hp = packbf(x0, x1);
    float h0 = __uint_as_float(hp << 16);
    float h1 = __uint_as_float(hp & 0xffff0000u);
    lp = packbf(x0 - h0, x1 - h1);
}

// m16n8k8 tf32 MMA (attention)
__device__ __forceinline__ void mma8(float* c, const uint32_t* a, const uint32_t* b) {
    asm volatile(
        "mma.sync.aligned.m16n8k8.row.col.f32.tf32.tf32.f32 "
        "{%0,%1,%2,%3}, {%4,%5,%6,%7}, {%8,%9}, {%0,%1,%2,%3};"
        : "+f"(c[0]), "+f"(c[1]), "+f"(c[2]), "+f"(c[3])
        : "r"(a[0]), "r"(a[1]), "r"(a[2]), "r"(a[3]), "r"(b[0]), "r"(b[1]));
}
// m16n8k16 bf16 MMA (projection)
__device__ __forceinline__ void mma16(float* c, const uint32_t* a, const uint32_t* b) {
    asm volatile(
        "mma.sync.aligned.m16n8k16.row.col.f32.bf16.bf16.f32 "
        "{%0,%1,%2,%3}, {%4,%5,%6,%7}, {%8,%9}, {%0,%1,%2,%3};"
        : "+f"(c[0]), "+f"(c[1]), "+f"(c[2]), "+f"(c[3])
        : "r"(a[0]), "r"(a[1]), "r"(a[2]), "r"(a[3]), "r"(b[0]), "r"(b[1]));
}

// fast exp2 on fma/alu pipes (no MUFU)
__device__ __forceinline__ float fexp2(float x) {
    x = fmaxf(x, -100.0f);
    float t = x + 12582912.0f;
    float f = x - (t - 12582912.0f);
    int   sc = __float_as_int(t) << 23;
    float p = 0.0013333558f;
    p = fmaf(p, f, 0.0096181291f);
    p = fmaf(p, f, 0.0555041087f);
    p = fmaf(p, f, 0.2402265069f);
    p = fmaf(p, f, 0.6931471806f);
    p = fmaf(p, f, 1.0f);
    return __int_as_float(__float_as_int(p) + sc);
}

// ---------------------------------------------------------------------------
// Kernel 0: split X into bf16 hi/lo packed pairs
// ---------------------------------------------------------------------------
__global__ __launch_bounds__(256) void k_cvt(const float* __restrict__ X) {
    size_t t = (size_t)blockIdx.x * 256 + threadIdx.x;  // one uint4 (8 floats)
    float4 v0 = *(const float4*)&X[t * 8];
    float4 v1 = *(const float4*)&X[t * 8 + 4];
    uint4 hp, lp;
    split2(v0.x, v0.y, hp.x, lp.x);
    split2(v0.z, v0.w, hp.y, lp.y);
    split2(v1.x, v1.y, hp.z, lp.z);
    split2(v1.z, v1.w, hp.w, lp.w);
    *(uint4*)&g_Xh[t * 4] = hp;
    *(uint4*)&g_Xl[t * 4] = lp;
}

// ---------------------------------------------------------------------------
// Kernel 1: Wc[h][e][d] = sum_l Wa[h][e][l]*Wt[h][l][d]  (fp32 exact),
//           epilogue writes bf16 hi/lo packed
// ---------------------------------------------------------------------------
__global__ __launch_bounds__(256) void k_wc(const float* __restrict__ Wt,
                                            const float* __restrict__ Wa) {
    const int h  = blockIdx.x;
    const int d0 = blockIdx.y * 128;
    __shared__ float Wa_s[64 * 36];
    __shared__ float Wt_s[32 * 132];

    const int tid = threadIdx.x;
    const int te = tid / 16;
    const int td = tid % 16;

    float acc[4][8];
#pragma unroll
    for (int i = 0; i < 4; i++)
#pragma unroll
        for (int j = 0; j < 8; j++) acc[i][j] = 0.f;

    for (int l0 = 0; l0 < LR; l0 += 32) {
#pragma unroll
        for (int it = 0; it < 2; it++) {
            int f = tid + it * 256;
            int e = f / 8, l4 = f % 8;
            float4 v = *(const float4*)&Wa[((size_t)h * 64 + e) * LR + l0 + l4 * 4];
            *(float4*)&Wa_s[e * 36 + l4 * 4] = v;
        }
#pragma unroll
        for (int it = 0; it < 4; it++) {
            int f = tid + it * 256;
            int l = f / 32, d4 = f % 32;
            float4 v = *(const float4*)&Wt[((size_t)h * LR + l0 + l) * HIDD + d0 + d4 * 4];
            *(float4*)&Wt_s[l * 132 + d4 * 4] = v;
        }
        __syncthreads();
#pragma unroll
        for (int l = 0; l < 32; l++) {
            float a[4];
#pragma unroll
            for (int i = 0; i < 4; i++) a[i] = Wa_s[(te * 4 + i) * 36 + l];
            float w[8];
            *(float4*)&w[0] = *(const float4*)&Wt_s[l * 132 + td * 8];
            *(float4*)&w[4] = *(const float4*)&Wt_s[l * 132 + td * 8 + 4];
#pragma unroll
            for (int i = 0; i < 4; i++)
#pragma unroll
                for (int j = 0; j < 8; j++) acc[i][j] = fmaf(a[i], w[j], acc[i][j]);
        }
        __syncthreads();
    }
#pragma unroll
    for (int i = 0; i < 4; i++) {
        uint4 hp, lp;
        split2(acc[i][0], acc[i][1], hp.x, lp.x);
        split2(acc[i][2], acc[i][3], hp.y, lp.y);
        split2(acc[i][4], acc[i][5], hp.z, lp.z);
        split2(acc[i][6], acc[i][7], hp.w, lp.w);
        size_t base = ((size_t)h * HD + te * 4 + i) * (HIDD / 2) + d0 / 2 + td * 4;
        *(uint4*)&g_Wh[base] = hp;
        *(uint4*)&g_Wl[base] = lp;
    }
}

// ---------------------------------------------------------------------------
// Kernel 2: t = X * Wc^T via bf16 split 3-term mma (near-fp32 precision)
// CTA: 128 n-rows x 64 e-cols of one (b,h). 8 warps (4m x 2n), K-tile 32.
// ---------------------------------------------------------------------------
#define PS_XH 0
#define PS_XL 2560
#define PS_WH 5120
#define PS_WL 6400
#define PS_SZ 7680          // u32 per stage
#define PROJ_SMEM_BYTES (2 * PS_SZ * 4)
#define NKIT  (HIDD / 32)   // 24

__global__ __launch_bounds__(256, 2) void k_proj_mma(int dummy) {
    extern __shared__ uint32_t su[];
    const uint32_t smb = smem_u32(su);

    const int bh = blockIdx.y, b = bh / NH, h = bh % NH;
    const int n0 = blockIdx.x * 128;
    const int tid = threadIdx.x, wid = tid >> 5, lid = tid & 31;
    const int mw = wid & 3, nw = wid >> 2;
    const int g = lid >> 2, t4 = lid & 3;
    const int mrow = mw * 32, ncol = nw * 32;

    const uint32_t* Xh = g_Xh + (size_t)(b * NSEQ + n0) * (HIDD / 2);
    const uint32_t* Xl = g_Xl + (size_t)(b * NSEQ + n0) * (HIDD / 2);
    const uint32_t* Wh = g_Wh + (size_t)h * HD * (HIDD / 2);
    const uint32_t* Wl = g_Wl + (size_t)h * HD * (HIDD / 2);

    // issue cp.async for k-iter ki into stage (ki & 1)
    auto issue = [&](int ki) {
        const int st = (ki & 1) * PS_SZ;
        const int k2 = ki * 16;
#pragma unroll
        for (int it = 0; it < 2; it++) {
            int f = tid + it * 256;
            int r = f >> 2, c4 = (f & 3) * 4;
            uint32_t d0 = smb + (uint32_t)(st + PS_XH + r * 20 + c4) * 4u;
            uint32_t d1 = smb + (uint32_t)(st + PS_XL + r * 20 + c4) * 4u;
            asm volatile("cp.async.cg.shared.global [%0], [%1], 16;"
                         :: "r"(d0), "l"(Xh + (size_t)r * (HIDD / 2) + k2 + c4));
            asm volatile("cp.async.cg.shared.global [%0], [%1], 16;"
                         :: "r"(d1), "l"(Xl + (size_t)r * (HIDD / 2) + k2 + c4));
        }
        {
            int r = tid >> 2, c4 = (tid & 3) * 4;
            uint32_t d0 = smb + (uint32_t)(st + PS_WH + r * 20 + c4) * 4u;
            uint32_t d1 = smb + (uint32_t)(st + PS_WL + r * 20 + c4) * 4u;
            asm volatile("cp.async.cg.shared.global [%0], [%1], 16;"
                         :: "r"(d0), "l"(Wh + (size_t)r * (HIDD / 2) + k2 + c4));
            asm volatile("cp.async.cg.shared.global [%0], [%1], 16;"
                         :: "r"(d1), "l"(Wl + (size_t)r * (HIDD / 2) + k2 + c4));
        }
        asm volatile("cp.async.commit_group;" ::: "memory");
    };

    float acc[2][4][4];
#pragma unroll
    for (int mi = 0; mi < 2; mi++)
#pragma unroll
        for (int nj = 0; nj < 4; nj++)
#pragma unroll
            for (int r = 0; r < 4; r++) acc[mi][nj][r] = 0.f;

    issue(0);
    for (int ki = 0; ki < NKIT; ki++) {
        if (ki + 1 < NKIT) {
            issue(ki + 1);
            asm volatile("cp.async.wait_group 1;" ::: "memory");
        } else {
            asm volatile("cp.async.wait_group 0;" ::: "memory");
        }
        __syncthreads();

        const uint32_t* S = su + (ki & 1) * PS_SZ;
#pragma unroll
        for (int kk = 0; kk < 2; kk++) {
            const int ko = kk * 8;
            uint32_t ah[2][4], al[2][4];
#pragma unroll
            for (int mi = 0; mi < 2; mi++) {
                int base = (mrow + mi * 16 + g) * 20 + ko + t4;
                ah[mi][0] = S[PS_XH + base];
                ah[mi][1] = S[PS_XH + base + 160];
                ah[mi][2] = S[PS_XH + base + 4];
                ah[mi][3] = S[PS_XH + base + 164];
                al[mi][0] = S[PS_XL + base];
                al[mi][1] = S[PS_XL + base + 160];
                al[mi][2] = S[PS_XL + base + 4];
                al[mi][3] = S[PS_XL + base + 164];
            }
#pragma unroll
            for (int nj = 0; nj < 4; nj++) {
                int bb = (ncol + nj * 8 + g) * 20 + ko + t4;
                uint32_t bhv[2] = { S[PS_WH + bb], S[PS_WH + bb + 4] };
                uint32_t blv[2] = { S[PS_WL + bb], S[PS_WL + bb + 4] };
#pragma unroll
                for (int mi = 0; mi < 2; mi++) {
                    mma16(acc[mi][nj], ah[mi], bhv);
                    mma16(acc[mi][nj], ah[mi], blv);
                    mma16(acc[mi][nj], al[mi], bhv);
                }
            }
        }
        __syncthreads();
    }

    // epilogue: write t fp32
    float* To = g_t + ((size_t)bh * NSEQ + n0) * HD;
#pragma unroll
    for (int mi = 0; mi < 2; mi++) {
        int r0 = mrow + mi * 16 + g;
#pragma unroll
        for (int nj = 0; nj < 4; nj++) {
            int c = ncol + nj * 8 + t4 * 2;
            *(float2*)&To[(size_t)r0 * HD + c] =
                make_float2(acc[mi][nj][0], acc[mi][nj][1]);
            *(float2*)&To[(size_t)(r0 + 8) * HD + c] =
                make_float2(acc[mi][nj][2], acc[mi][nj][3]);
        }
    }
}

// ---------------------------------------------------------------------------
// Kernel 3: tf32 mma.sync flash attention (unchanged from round 4)
// ---------------------------------------------------------------------------
#define OF_Q   0
#define OF_K0  8704
#define OF_K1  13056
#define OF_P   17408
#define OF_B   26112
#define OF_L   26240
#define ATT_SMEM_BYTES (26496 * 4)

#define QSCALE 0.05205654442f
#define SBIAS  (-12.0f)

__device__ __forceinline__ void issue_tile(uint32_t dstb, const float* src, int tid) {
#pragma unroll
    for (int it = 0; it < 4; it++) {
        int f = tid + it * 256;
        int r = f >> 4, c4 = f & 15;
        uint32_t dst = dstb + (uint32_t)(r * 68 + c4 * 4) * 4u;
        asm volatile("cp.async.cg.shared.global [%0], [%1], 16;"
                     :: "r"(dst), "l"(src + (size_t)r * HD + c4 * 4));
    }
    asm volatile("cp.async.commit_group;" ::: "memory");
}

__global__ __launch_bounds__(256, 2) void k_attn3(const int* __restrict__ amask,
                                                  float* __restrict__ out) {
    extern __shared__ float sm[];
    float* Qs   = sm + OF_Q;
    float* Ps   = sm + OF_P;
    float* lred = sm + OF_L;
    const uint32_t smb = smem_u32(sm);

    const int bh = blockIdx.y, b = bh / NH, h = bh % NH;
    const int q0 = blockIdx.x * QT;
    const int tid = threadIdx.x, wid = tid >> 5, lid = tid & 31;
    const int mw = wid & 3, nw = wid >> 2;
    const int g = lid >> 2, t4 = lid & 3;
    const int mrow = mw * 32, ncol = nw * 32;

    const float* Tq = g_t + (size_t)bh * NSEQ * HD;
    const int*   mb = amask + (size_t)b * NSEQ;

    issue_tile(smb + OF_K0 * 4, Tq, tid);
    if (tid < 64) sm[OF_B + tid] = (mb[tid] == 0) ? -3000.f : SBIAS;

#pragma unroll
    for (int it = 0; it < 8; it++) {
        int f = tid + it * 256;
        int r = f >> 4, c4 = f & 15;
        float4 v = *(const float4*)&Tq[(size_t)(q0 + r) * HD + c4 * 4];
        float4 w;
        w.x = __uint_as_float(cvt_tf32(v.x * QSCALE));
        w.y = __uint_as_float(cvt_tf32(v.y * QSCALE));
        w.z = __uint_as_float(cvt_tf32(v.z * QSCALE));
        w.w = __uint_as_float(cvt_tf32(v.w * QSCALE));
        *(float4*)&Qs[r * 68 + c4 * 4] = w;
    }

    float rs[4] = {0.f, 0.f, 0.f, 0.f};
    float oacc[2][4][4];
#pragma unroll
    for (int mi = 0; mi < 2; mi++)
#pragma unroll
        for (int nj = 0; nj < 4; nj++)
#pragma unroll
            for (int r = 0; r < 4; r++) oacc[mi][nj][r] = 0.f;

    for (int i = 0; i < NIT; i++) {
        asm volatile("cp.async.wait_group 0;" ::: "memory");
        __syncthreads();
        if (i + 1 < NIT) {
            issue_tile(smb + (((i + 1) & 1) ? OF_K1 : OF_K0) * 4,
                       Tq + (size_t)(i + 1) * KT * HD, tid);
            if (tid < 64)
                sm[OF_B + ((i + 1) & 1) * 64 + tid] =
                    (mb[(i + 1) * KT + tid] == 0) ? -3000.f : SBIAS;
        }
        const float* Kc   = sm + ((i & 1) ? OF_K1 : OF_K0);
        const float* bias = sm + OF_B + (i & 1) * 64;

        float sacc[2][4][4];
#pragma unroll
        for (int mi = 0; mi < 2; mi++)
#pragma unroll
            for (int nj = 0; nj < 4; nj++)
#pragma unroll
                for (int r = 0; r < 4; r++) sacc[mi][nj][r] = 0.f;

#pragma unroll
        for (int k8 = 0; k8 < 8; k8++) {
            uint32_t a[2][4];
#pragma unroll
            for (int mi = 0; mi < 2; mi++) {
                const float* qp = Qs + (mrow + mi * 16 + g) * 68 + k8 * 8 + t4;
                a[mi][0] = fbits(qp[0]);
                a[mi][1] = fbits(qp[8 * 68]);
                a[mi][2] = fbits(qp[4]);
                a[mi][3] = fbits(qp[8 * 68 + 4]);
            }
#pragma unroll
            for (int nj = 0; nj < 4; nj++) {
                const float* kp = Kc + (ncol + nj * 8 + g) * 68 + k8 * 8 + t4;
                uint32_t bf[2] = { fbits(kp[0]), fbits(kp[4]) };
                mma8(sacc[0][nj], a[0], bf);
                mma8(sacc[1][nj], a[1], bf);
            }
        }

#pragma unroll
        for (int mi = 0; mi < 2; mi++)
#pragma unroll
            for (int nj = 0; nj < 4; nj++) {
                float2 bv = *(const float2*)&bias[nj * 8 + t4 * 2];
                uint32_t u0 = cvt_tf32(fexp2(sacc[mi][nj][0] + bv.x));
                uint32_t u1 = cvt_tf32(fexp2(sacc[mi][nj][1] + bv.y));
                uint32_t u2 = cvt_tf32(fexp2(sacc[mi][nj][2] + bv.x));
                uint32_t u3 = cvt_tf32(fexp2(sacc[mi][nj][3] + bv.y));
                rs[mi * 2 + 0] += __uint_as_float(u0) + __uint_as_float(u1);
                rs[mi * 2 + 1] += __uint_as_float(u2) + __uint_as_float(u3);
                float* pp = Ps + (mrow + mi * 16 + g) * 68 + ncol + nj * 8 + t4 * 2;
                *(float2*)pp = make_float2(__uint_as_float(u0), __uint_as_float(u1));
                *(float2*)(pp + 8 * 68) =
                    make_float2(__uint_as_float(u2), __uint_as_float(u3));
            }
        __syncthreads();

#pragma unroll
        for (int k8 = 0; k8 < 8; k8++) {
            uint32_t a[2][4];
#pragma unroll
            for (int mi = 0; mi < 2; mi++) {
                const float* pp = Ps + (mrow + mi * 16 + g) * 68 + k8 * 8 + t4;
                a[mi][0] = fbits(pp[0]);
                a[mi][1] = fbits(pp[8 * 68]);
                a[mi][2] = fbits(pp[4]);
                a[mi][3] = fbits(pp[8 * 68 + 4]);
            }
#pragma unroll
            for (int nj = 0; nj < 4; nj++) {
                const float* vp = Kc + (k8 * 8 + t4) * 68 + ncol + nj * 8 + g;
                uint32_t bf[2] = { fbits(vp[0]), fbits(vp[4 * 68]) };
                mma8(oacc[0][nj], a[0], bf);
                mma8(oacc[1][nj], a[1], bf);
            }
        }
    }

#pragma unroll
    for (int r = 0; r < 4; r++) {
        rs[r] += __shfl_xor_sync(0xffffffffu, rs[r], 1);
        rs[r] += __shfl_xor_sync(0xffffffffu, rs[r], 2);
    }
    if (t4 == 0) {
#pragma unroll
        for (int r = 0; r < 4; r++)
            lred[nw * 128 + mrow + (r >> 1) * 16 + (r & 1) * 8 + g] = rs[r];
    }
    __syncthreads();

#pragma unroll
    for (int mi = 0; mi < 2; mi++) {
        int r0 = mrow + mi * 16 + g;
        float inv0 = 1.f / (lred[r0] + lred[128 + r0]);
        float inv1 = 1.f / (lred[r0 + 8] + lred[128 + r0 + 8]);
        float* ob0 = out + ((size_t)b * NSEQ + q0 + r0) * (NH * HD) + h * HD + ncol;
        float* ob1 = ob0 + (size_t)8 * (NH * HD);
#pragma unroll
        for (int nj = 0; nj < 4; nj++) {
            *(float2*)&ob0[nj * 8 + t4 * 2] =
                make_float2(oacc[mi][nj][0] * inv0, oacc[mi][nj][1] * inv0);
            *(float2*)&ob1[nj * 8 + t4 * 2] =
                make_float2(oacc[mi][nj][2] * inv1, oacc[mi][nj][3] * inv1);
        }
    }
}

// ---------------------------------------------------------------------------
extern "C" void kernel_launch(void* const* d_in, const int* in_sizes, int n_in,
                              void* d_out, int out_size) {
    const float* hidden = (const float*)d_in[0];
    const int*   amask  = (const int*)d_in[1];
    const float* Wt     = (const float*)d_in[2];
    const float* Wa     = (const float*)d_in[3];
    float* out = (float*)d_out;

    k_cvt<<<NB * NSEQ * HIDD / (256 * 8), 256>>>(hidden);
    k_wc<<<dim3(NH, HIDD / 128), 256>>>(Wt, Wa);

    cudaFuncSetAttribute(k_proj_mma, cudaFuncAttributeMaxDynamicSharedMemorySize,
                         PROJ_SMEM_BYTES);
    k_proj_mma<<<dim3(NSEQ / 128, NB * NH), 256, PROJ_SMEM_BYTES>>>(0);

    cudaFuncSetAttribute(k_attn3, cudaFuncAttributeMaxDynamicSharedMemorySize,
                         ATT_SMEM_BYTES);
    k_attn3<<<dim3(NSEQ / QT, NB * NH), 256, ATT_SMEM_BYTES>>>(amask, out);
}

// round 6
// speedup vs baseline: 2.8476x; 1.0177x over previous
#include <cuda_runtime.h>
#include <cuda_bf16.h>
#include <cstdint>

#define NB    8
#define NSEQ  1024
#define HIDD  768
#define NH    12
#define LR    256
#define HD    64

#define QT    128
#define KT    64
#define NIT   (NSEQ / KT)

// scratch (no cudaMalloc allowed)
__device__ uint32_t g_Xh[NB * NSEQ * (HIDD / 2)];   // X bf16 hi, k-pair packed
__device__ uint32_t g_Xl[NB * NSEQ * (HIDD / 2)];
__device__ uint32_t g_Wh[NH * HD * (HIDD / 2)];     // Wc bf16 hi
__device__ uint32_t g_Wl[NH * HD * (HIDD / 2)];
__device__ uint32_t g_th[NB * NH * NSEQ * (HD / 2)]; // t bf16 hi, e-pair packed
__device__ uint32_t g_tl[NB * NH * NSEQ * (HD / 2)]; // t bf16 lo

// ---------------------------------------------------------------------------
// helpers
// ---------------------------------------------------------------------------
__device__ __forceinline__ uint32_t smem_u32(const void* p) {
    uint32_t a;
    asm("{ .reg .u64 t; cvta.to.shared.u64 t, %1; cvt.u32.u64 %0, t; }"
        : "=r"(a) : "l"(p));
    return a;
}
// pack two floats to bf16x2: low half = first arg
__device__ __forceinline__ uint32_t packbf(float lo, float hi) {
    uint32_t r;
    asm("cvt.rn.bf16x2.f32 %0, %1, %2;" : "=r"(r) : "f"(hi), "f"(lo));
    return r;
}
__device__ __forceinline__ void split2(float x0, float x1,
                                       uint32_t& hp, uint32_t& lp) {
    hp = packbf(x0, x1);
    float h0 = __uint_as_float(hp << 16);
    float h1 = __uint_as_float(hp & 0xffff0000u);
    lp = packbf(x0 - h0, x1 - h1);
}
__device__ __forceinline__ void mma16(float* c, const uint32_t* a, const uint32_t* b) {
    asm volatile(
        "mma.sync.aligned.m16n8k16.row.col.f32.bf16.bf16.f32 "
        "{%0,%1,%2,%3}, {%4,%5,%6,%7}, {%8,%9}, {%0,%1,%2,%3};"
        : "+f"(c[0]), "+f"(c[1]), "+f"(c[2]), "+f"(c[3])
        : "r"(a[0]), "r"(a[1]), "r"(a[2]), "r"(a[3]), "r"(b[0]), "r"(b[1]));
}
__device__ __forceinline__ void ldsm4(uint32_t* r, uint32_t a) {
    asm volatile("ldmatrix.sync.aligned.m8n8.x4.b16 {%0,%1,%2,%3}, [%4];"
        : "=r"(r[0]), "=r"(r[1]), "=r"(r[2]), "=r"(r[3]) : "r"(a));
}
__device__ __forceinline__ void ldsm4t(uint32_t* r, uint32_t a) {
    asm volatile("ldmatrix.sync.aligned.m8n8.x4.trans.b16 {%0,%1,%2,%3}, [%4];"
        : "=r"(r[0]), "=r"(r[1]), "=r"(r[2]), "=r"(r[3]) : "r"(a));
}
// fast exp2 on fma/alu pipes (no MUFU)
__device__ __forceinline__ float fexp2(float x) {
    x = fmaxf(x, -100.0f);
    float t = x + 12582912.0f;
    float f = x - (t - 12582912.0f);
    int   sc = __float_as_int(t) << 23;
    float p = 0.0013333558f;
    p = fmaf(p, f, 0.0096181291f);
    p = fmaf(p, f, 0.0555041087f);
    p = fmaf(p, f, 0.2402265069f);
    p = fmaf(p, f, 0.6931471806f);
    p = fmaf(p, f, 1.0f);
    return __int_as_float(__float_as_int(p) + sc);
}

// ---------------------------------------------------------------------------
// Kernel 0: split X into bf16 hi/lo packed pairs
// ---------------------------------------------------------------------------
__global__ __launch_bounds__(256) void k_cvt(const float* __restrict__ X) {
    size_t t = (size_t)blockIdx.x * 256 + threadIdx.x;
    float4 v0 = *(const float4*)&X[t * 8];
    float4 v1 = *(const float4*)&X[t * 8 + 4];
    uint4 hp, lp;
    split2(v0.x, v0.y, hp.x, lp.x);
    split2(v0.z, v0.w, hp.y, lp.y);
    split2(v1.x, v1.y, hp.z, lp.z);
    split2(v1.z, v1.w, hp.w, lp.w);
    *(uint4*)&g_Xh[t * 4] = hp;
    *(uint4*)&g_Xl[t * 4] = lp;
}

// ---------------------------------------------------------------------------
// Kernel 1: Wc = Wa @ Wt (fp32 exact), epilogue writes bf16 hi/lo
// ---------------------------------------------------------------------------
__global__ __launch_bounds__(256) void k_wc(const float* __restrict__ Wt,
                                            const float* __restrict__ Wa) {
    const int h  = blockIdx.x;
    const int d0 = blockIdx.y * 128;
    __shared__ float Wa_s[64 * 36];
    __shared__ float Wt_s[32 * 132];

    const int tid = threadIdx.x;
    const int te = tid / 16;
    const int td = tid % 16;

    float acc[4][8];
#pragma unroll
    for (int i = 0; i < 4; i++)
#pragma unroll
        for (int j = 0; j < 8; j++) acc[i][j] = 0.f;

    for (int l0 = 0; l0 < LR; l0 += 32) {
#pragma unroll
        for (int it = 0; it < 2; it++) {
            int f = tid + it * 256;
            int e = f / 8, l4 = f % 8;
            float4 v = *(const float4*)&Wa[((size_t)h * 64 + e) * LR + l0 + l4 * 4];
            *(float4*)&Wa_s[e * 36 + l4 * 4] = v;
        }
#pragma unroll
        for (int it = 0; it < 4; it++) {
            int f = tid + it * 256;
            int l = f / 32, d4 = f % 32;
            float4 v = *(const float4*)&Wt[((size_t)h * LR + l0 + l) * HIDD + d0 + d4 * 4];
            *(float4*)&Wt_s[l * 132 + d4 * 4] = v;
        }
        __syncthreads();
#pragma unroll
        for (int l = 0; l < 32; l++) {
            float a[4];
#pragma unroll
            for (int i = 0; i < 4; i++) a[i] = Wa_s[(te * 4 + i) * 36 + l];
            float w[8];
            *(float4*)&w[0] = *(const float4*)&Wt_s[l * 132 + td * 8];
            *(float4*)&w[4] = *(const float4*)&Wt_s[l * 132 + td * 8 + 4];
#pragma unroll
            for (int i = 0; i < 4; i++)
#pragma unroll
                for (int j = 0; j < 8; j++) acc[i][j] = fmaf(a[i], w[j], acc[i][j]);
        }
        __syncthreads();
    }
#pragma unroll
    for (int i = 0; i < 4; i++) {
        uint4 hp, lp;
        split2(acc[i][0], acc[i][1], hp.x, lp.x);
        split2(acc[i][2], acc[i][3], hp.y, lp.y);
        split2(acc[i][4], acc[i][5], hp.z, lp.z);
        split2(acc[i][6], acc[i][7], hp.w, lp.w);
        size_t base = ((size_t)h * HD + te * 4 + i) * (HIDD / 2) + d0 / 2 + td * 4;
        *(uint4*)&g_Wh[base] = hp;
        *(uint4*)&g_Wl[base] = lp;
    }
}

// ---------------------------------------------------------------------------
// Kernel 2: t = X * Wc^T via bf16 split 3-term mma; writes g_th/g_tl
// ---------------------------------------------------------------------------
#define PS_XH 0
#define PS_XL 2560
#define PS_WH 5120
#define PS_WL 6400
#define PS_SZ 7680
#define PROJ_SMEM_BYTES (2 * PS_SZ * 4)
#define NKIT  (HIDD / 32)

__global__ __launch_bounds__(256, 2) void k_proj_mma(int dummy) {
    extern __shared__ uint32_t su[];
    const uint32_t smb = smem_u32(su);

    const int bh = blockIdx.y, b = bh / NH, h = bh % NH;
    const int n0 = blockIdx.x * 128;
    const int tid = threadIdx.x, wid = tid >> 5, lid = tid & 31;
    const int mw = wid & 3, nw = wid >> 2;
    const int g = lid >> 2, t4 = lid & 3;
    const int mrow = mw * 32, ncol = nw * 32;

    const uint32_t* Xh = g_Xh + (size_t)(b * NSEQ + n0) * (HIDD / 2);
    const uint32_t* Xl = g_Xl + (size_t)(b * NSEQ + n0) * (HIDD / 2);
    const uint32_t* Wh = g_Wh + (size_t)h * HD * (HIDD / 2);
    const uint32_t* Wl = g_Wl + (size_t)h * HD * (HIDD / 2);

    auto issue = [&](int ki) {
        const int st = (ki & 1) * PS_SZ;
        const int k2 = ki * 16;
#pragma unroll
        for (int it = 0; it < 2; it++) {
            int f = tid + it * 256;
            int r = f >> 2, c4 = (f & 3) * 4;
            uint32_t d0 = smb + (uint32_t)(st + PS_XH + r * 20 + c4) * 4u;
            uint32_t d1 = smb + (uint32_t)(st + PS_XL + r * 20 + c4) * 4u;
            asm volatile("cp.async.cg.shared.global [%0], [%1], 16;"
                         :: "r"(d0), "l"(Xh + (size_t)r * (HIDD / 2) + k2 + c4));
            asm volatile("cp.async.cg.shared.global [%0], [%1], 16;"
                         :: "r"(d1), "l"(Xl + (size_t)r * (HIDD / 2) + k2 + c4));
        }
        {
            int r = tid >> 2, c4 = (tid & 3) * 4;
            uint32_t d0 = smb + (uint32_t)(st + PS_WH + r * 20 + c4) * 4u;
            uint32_t d1 = smb + (uint32_t)(st + PS_WL + r * 20 + c4) * 4u;
            asm volatile("cp.async.cg.shared.global [%0], [%1], 16;"
                         :: "r"(d0), "l"(Wh + (size_t)r * (HIDD / 2) + k2 + c4));
            asm volatile("cp.async.cg.shared.global [%0], [%1], 16;"
                         :: "r"(d1), "l"(Wl + (size_t)r * (HIDD / 2) + k2 + c4));
        }
        asm volatile("cp.async.commit_group;" ::: "memory");
    };

    float acc[2][4][4];
#pragma unroll
    for (int mi = 0; mi < 2; mi++)
#pragma unroll
        for (int nj = 0; nj < 4; nj++)
#pragma unroll
            for (int r = 0; r < 4; r++) acc[mi][nj][r] = 0.f;

    issue(0);
    for (int ki = 0; ki < NKIT; ki++) {
        if (ki + 1 < NKIT) {
            issue(ki + 1);
            asm volatile("cp.async.wait_group 1;" ::: "memory");
        } else {
            asm volatile("cp.async.wait_group 0;" ::: "memory");
        }
        __syncthreads();

        const uint32_t* S = su + (ki & 1) * PS_SZ;
#pragma unroll
        for (int kk = 0; kk < 2; kk++) {
            const int ko = kk * 8;
            uint32_t ah[2][4], al[2][4];
#pragma unroll
            for (int mi = 0; mi < 2; mi++) {
                int base = (mrow + mi * 16 + g) * 20 + ko + t4;
                ah[mi][0] = S[PS_XH + base];
                ah[mi][1] = S[PS_XH + base + 160];
                ah[mi][2] = S[PS_XH + base + 4];
                ah[mi][3] = S[PS_XH + base + 164];
                al[mi][0] = S[PS_XL + base];
                al[mi][1] = S[PS_XL + base + 160];
                al[mi][2] = S[PS_XL + base + 4];
                al[mi][3] = S[PS_XL + base + 164];
            }
#pragma unroll
            for (int nj = 0; nj < 4; nj++) {
                int bb = (ncol + nj * 8 + g) * 20 + ko + t4;
                uint32_t bhv[2] = { S[PS_WH + bb], S[PS_WH + bb + 4] };
                uint32_t blv[2] = { S[PS_WL + bb], S[PS_WL + bb + 4] };
#pragma unroll
                for (int mi = 0; mi < 2; mi++) {
                    mma16(acc[mi][nj], ah[mi], bhv);
                    mma16(acc[mi][nj], ah[mi], blv);
                    mma16(acc[mi][nj], al[mi], bhv);
                }
            }
        }
        __syncthreads();
    }

    // epilogue: split to bf16 hi/lo and write packed e-pairs
    uint32_t* Oh = g_th + ((size_t)bh * NSEQ + n0) * (HD / 2);
    uint32_t* Ol = g_tl + ((size_t)bh * NSEQ + n0) * (HD / 2);
#pragma unroll
    for (int mi = 0; mi < 2; mi++) {
        int r0 = mrow + mi * 16 + g;
#pragma unroll
        for (int nj = 0; nj < 4; nj++) {
            int cu = (ncol + nj * 8) / 2 + t4;
            uint32_t hp, lp;
            split2(acc[mi][nj][0], acc[mi][nj][1], hp, lp);
            Oh[(size_t)r0 * (HD / 2) + cu] = hp;
            Ol[(size_t)r0 * (HD / 2) + cu] = lp;
            split2(acc[mi][nj][2], acc[mi][nj][3], hp, lp);
            Oh[(size_t)(r0 + 8) * (HD / 2) + cu] = hp;
            Ol[(size_t)(r0 + 8) * (HD / 2) + cu] = lp;
        }
    }
}

// ---------------------------------------------------------------------------
// Kernel 3: bf16-split flash attention, register-resident P, ldmatrix.
// CTA = 128 q rows of one (b,h); 8 warps (mw = q 32-block, nw = key 32-half).
// Each warp: S(32q x 32key) 3-term; exp -> packed bf16 B-frags (in regs);
// PV: O^T(e-half nw x 32q) over ALL 64 keys (partner frags via tiny smem).
// ---------------------------------------------------------------------------
// smem byte offsets (row stride 144B for ldmatrix conflict-freedom)
#define OQH   0                     // 128*144
#define OQL   18432
#define OKT   36864                 // 4 tiles (stage,copy) * 64*144
#define OP    73728                 // u32[4mw][4kb][4qb][2][32] = 16384 B
#define OBIAS 90112                 // float[2][64]
#define OLRED 90624                 // float[2][128]
#define ATT_SMEM 91648

#define CE 0.052058774f             // 768^-0.5 * log2(e)

__global__ __launch_bounds__(256, 2) void k_attn4(const int* __restrict__ amask,
                                                  float* __restrict__ out) {
    extern __shared__ __align__(128) char smem[];
    const uint32_t smb = smem_u32(smem);

    const int bh = blockIdx.y, b = bh / NH, h = bh % NH;
    const int q0 = blockIdx.x * QT;
    const int tid = threadIdx.x, wid = tid >> 5, lid = tid & 31;
    const int g = lid >> 2, t4 = lid & 3;
    const int mw = wid & 3, nw = wid >> 2;
    const int mrow = mw * 32;
    const int lane7 = lid & 7;
    const int lane8 = (lid & 8) ? 8 : 0;
    const int lane16 = (lid & 16) ? 8 : 0;

    const uint32_t* Th = g_th + (size_t)bh * NSEQ * (HD / 2);
    const uint32_t* Tl = g_tl + (size_t)bh * NSEQ * (HD / 2);
    const int* mb = amask + (size_t)b * NSEQ;
    float* biasf = (float*)(smem + OBIAS);

    // ---- prologue: Q (hi+lo) + K tile 0 + bias 0 ----
#pragma unroll
    for (int it = 0; it < 8; it++) {
        int f = tid + it * 256;
        int cp = f >> 10, r = (f >> 3) & 127, c = f & 7;
        uint32_t dst = smb + (cp ? OQL : OQH) + (uint32_t)(r * 144 + c * 16);
        const uint32_t* src = (cp ? Tl : Th) + (size_t)(q0 + r) * 32 + c * 4;
        asm volatile("cp.async.cg.shared.global [%0], [%1], 16;"
                     :: "r"(dst), "l"(src));
    }
    asm volatile("cp.async.commit_group;" ::: "memory");
#pragma unroll
    for (int it = 0; it < 4; it++) {
        int f = tid + it * 256;
        int cp = f >> 9, r = (f >> 3) & 63, c = f & 7;
        uint32_t dst = smb + OKT + cp * 9216 + (uint32_t)(r * 144 + c * 16);
        const uint32_t* src = (cp ? Tl : Th) + (size_t)r * 32 + c * 4;
        asm volatile("cp.async.cg.shared.global [%0], [%1], 16;"
                     :: "r"(dst), "l"(src));
    }
    asm volatile("cp.async.commit_group;" ::: "memory");
    if (tid < 64) biasf[tid] = (mb[tid] == 0) ? -3000.f : -12.f;

    float rs[4] = {0.f, 0.f, 0.f, 0.f};
    float oacc[2][4][4];
#pragma unroll
    for (int me = 0; me < 2; me++)
#pragma unroll
        for (int qb = 0; qb < 4; qb++)
#pragma unroll
            for (int r = 0; r < 4; r++) oacc[me][qb][r] = 0.f;

    uint32_t* Ps = (uint32_t*)(smem + OP);

    for (int i = 0; i < NIT; i++) {
        asm volatile("cp.async.wait_group 0;" ::: "memory");
        __syncthreads();

        // prefetch next K tile + bias
        if (i + 1 < NIT) {
            int j0 = (i + 1) * KT;
#pragma unroll
            for (int it = 0; it < 4; it++) {
                int f = tid + it * 256;
                int cp = f >> 9, r = (f >> 3) & 63, c = f & 7;
                uint32_t dst = smb + OKT + ((i + 1) & 1) * 18432 + cp * 9216
                             + (uint32_t)(r * 144 + c * 16);
                const uint32_t* src = (cp ? Tl : Th) + (size_t)(j0 + r) * 32 + c * 4;
                asm volatile("cp.async.cg.shared.global [%0], [%1], 16;"
                             :: "r"(dst), "l"(src));
            }
            asm volatile("cp.async.commit_group;" ::: "memory");
            if (tid < 64)
                biasf[((i + 1) & 1) * 64 + tid] =
                    (mb[j0 + tid] == 0) ? -3000.f : -12.f;
        }

        const uint32_t kh_b = smb + OKT + (i & 1) * 18432;
        const uint32_t kl_b = kh_b + 9216;

        // ---- S = Q K^T, 3-term bf16 (32q x 32key this warp) ----
        float sacc[2][4][4];
#pragma unroll
        for (int mi = 0; mi < 2; mi++)
#pragma unroll
            for (int nj = 0; nj < 4; nj++)
#pragma unroll
                for (int r = 0; r < 4; r++) sacc[mi][nj][r] = 0.f;

#pragma unroll
        for (int kb = 0; kb < 4; kb++) {
            uint32_t kh[2][4], kl[2][4];
#pragma unroll
            for (int s = 0; s < 2; s++) {
                uint32_t ro = (uint32_t)((nw * 32 + s * 16 + lane7 + lane16) * 144
                                         + (kb * 16 + lane8) * 2);
                ldsm4(kh[s], kh_b + ro);
                ldsm4(kl[s], kl_b + ro);
            }
#pragma unroll
            for (int mi = 0; mi < 2; mi++) {
                uint32_t ro = (uint32_t)((mrow + mi * 16 + lane7 + lane8) * 144
                                         + (kb * 16 + lane16) * 2);
                uint32_t qh[4], ql[4];
                ldsm4(qh, smb + OQH + ro);
                ldsm4(ql, smb + OQL + ro);
#pragma unroll
                for (int s = 0; s < 2; s++)
#pragma unroll
                    for (int j = 0; j < 2; j++) {
                        uint32_t bh2[2] = { kh[s][j * 2], kh[s][j * 2 + 1] };
                        uint32_t bl2[2] = { kl[s][j * 2], kl[s][j * 2 + 1] };
                        float* c = sacc[mi][s * 2 + j];
                        mma16(c, qh, bh2);
                        mma16(c, ql, bh2);
                        mma16(c, qh, bl2);
                    }
            }
        }

        // ---- exp2 (static bias) -> packed bf16 PV B-frags (registers) ----
        uint32_t pfr[2][4][2];   // [kb_local][qb][breg]
        const float* bi = biasf + (i & 1) * 64 + nw * 32;
#pragma unroll
        for (int mi = 0; mi < 2; mi++)
#pragma unroll
            for (int nj = 0; nj < 4; nj++) {
                float bx = bi[nj * 8 + 2 * t4];
                float by = bi[nj * 8 + 2 * t4 + 1];
                float* c = sacc[mi][nj];
                float p0 = fexp2(fmaf(c[0], CE, bx));
                float p1 = fexp2(fmaf(c[1], CE, by));
                float p2 = fexp2(fmaf(c[2], CE, bx));
                float p3 = fexp2(fmaf(c[3], CE, by));
                uint32_t u01 = packbf(p0, p1);
                uint32_t u23 = packbf(p2, p3);
                // row sums from the ROUNDED values (self-consistent softmax)
                rs[mi * 2 + 0] += __uint_as_float(u01 << 16)
                                + __uint_as_float(u01 & 0xffff0000u);
                rs[mi * 2 + 1] += __uint_as_float(u23 << 16)
                                + __uint_as_float(u23 & 0xffff0000u);
                pfr[nj >> 1][mi * 2 + 0][nj & 1] = u01;
                pfr[nj >> 1][mi * 2 + 1][nj & 1] = u23;
            }
        // share frags with the partner warp (other key half, same q rows)
#pragma unroll
        for (int kbl = 0; kbl < 2; kbl++)
#pragma unroll
            for (int qb = 0; qb < 4; qb++)
#pragma unroll
                for (int br = 0; br < 2; br++)
                    Ps[(((mw * 4 + nw * 2 + kbl) * 4 + qb) * 2 + br) * 32 + lid] =
                        pfr[kbl][qb][br];
        __syncthreads();

        // ---- O^T += V^T P^T over all 64 keys (e-half = nw) ----
#pragma unroll
        for (int kbg = 0; kbg < 4; kbg++) {
            uint32_t bfr[4][2];
            if ((kbg >> 1) == nw) {
#pragma unroll
                for (int qb = 0; qb < 4; qb++) {
                    bfr[qb][0] = pfr[kbg & 1][qb][0];
                    bfr[qb][1] = pfr[kbg & 1][qb][1];
                }
            } else {
#pragma unroll
                for (int qb = 0; qb < 4; qb++)
#pragma unroll
                    for (int br = 0; br < 2; br++)
                        bfr[qb][br] =
                            Ps[(((mw * 4 + kbg) * 4 + qb) * 2 + br) * 32 + lid];
            }
            uint32_t ro = (uint32_t)((kbg * 16 + lane7 + lane16) * 144
                                     + (nw * 32 + lane8) * 2);
#pragma unroll
            for (int me = 0; me < 2; me++) {
                uint32_t ah[4], al[4];
                ldsm4t(ah, kh_b + ro + me * 32);
                ldsm4t(al, kl_b + ro + me * 32);
#pragma unroll
                for (int qb = 0; qb < 4; qb++) {
                    mma16(oacc[me][qb], ah, bfr[qb]);
                    mma16(oacc[me][qb], al, bfr[qb]);
                }
            }
        }
    }

    // ---- epilogue ----
#pragma unroll
    for (int r = 0; r < 4; r++) {
        rs[r] += __shfl_xor_sync(0xffffffffu, rs[r], 1);
        rs[r] += __shfl_xor_sync(0xffffffffu, rs[r], 2);
    }
    float* lred = (float*)(smem + OLRED);
    if (t4 == 0) {
#pragma unroll
        for (int r = 0; r < 4; r++)
            lred[nw * 128 + mrow + (r >> 1) * 16 + (r & 1) * 8 + g] = rs[r];
    }
    __syncthreads();

#pragma unroll
    for (int me = 0; me < 2; me++)
#pragma unroll
        for (int qb = 0; qb < 4; qb++) {
            int qa = mrow + qb * 8 + 2 * t4;
            float inva = 1.f / (lred[qa] + lred[128 + qa]);
            float invb = 1.f / (lred[qa + 1] + lred[128 + qa + 1]);
            int e0 = nw * 32 + me * 16 + g;
            float* o = out + ((size_t)b * NSEQ + q0 + qa) * (NH * HD) + h * HD;
            o[e0]               = oacc[me][qb][0] * inva;
            o[NH * HD + e0]     = oacc[me][qb][1] * invb;
            o[e0 + 8]           = oacc[me][qb][2] * inva;
            o[NH * HD + e0 + 8] = oacc[me][qb][3] * invb;
        }
}

// ---------------------------------------------------------------------------
extern "C" void kernel_launch(void* const* d_in, const int* in_sizes, int n_in,
                              void* d_out, int out_size) {
    const float* hidden = (const float*)d_in[0];
    const int*   amask  = (const int*)d_in[1];
    const float* Wt     = (const float*)d_in[2];
    const float* Wa     = (const float*)d_in[3];
    float* out = (float*)d_out;

    k_cvt<<<NB * NSEQ * HIDD / (256 * 8), 256>>>(hidden);
    k_wc<<<dim3(NH, HIDD / 128), 256>>>(Wt, Wa);

    cudaFuncSetAttribute(k_proj_mma, cudaFuncAttributeMaxDynamicSharedMemorySize,
                         PROJ_SMEM_BYTES);
    k_proj_mma<<<dim3(NSEQ / 128, NB * NH), 256, PROJ_SMEM_BYTES>>>(0);

    cudaFuncSetAttribute(k_attn4, cudaFuncAttributeMaxDynamicSharedMemorySize,
                         ATT_SMEM);
    k_attn4<<<dim3(NSEQ / QT, NB * NH), 256, ATT_SMEM>>>(amask, out);
}

// round 7
// speedup vs baseline: 3.0542x; 1.0725x over previous
#include <cuda_runtime.h>
#include <cuda_bf16.h>
#include <cstdint>

#define NB    8
#define NSEQ  1024
#define HIDD  768
#define NH    12
#define LR    256
#define HD    64

#define QT    128
#define KT    64
#define NIT   (NSEQ / KT)

// scratch (no cudaMalloc allowed)
__device__ uint32_t g_Xh[NB * NSEQ * (HIDD / 2)];    // X bf16 hi, k-pair packed
__device__ uint32_t g_Xl[NB * NSEQ * (HIDD / 2)];
__device__ uint32_t g_Wh[NH * HD * (HIDD / 2)];      // Wc bf16 hi
__device__ uint32_t g_Wl[NH * HD * (HIDD / 2)];
__device__ uint32_t g_th[NB * NH * NSEQ * (HD / 2)]; // t bf16 hi, e-pair packed
__device__ uint32_t g_tl[NB * NH * NSEQ * (HD / 2)]; // t bf16 lo

// ---------------------------------------------------------------------------
// helpers
// ---------------------------------------------------------------------------
__device__ __forceinline__ uint32_t smem_u32(const void* p) {
    uint32_t a;
    asm("{ .reg .u64 t; cvta.to.shared.u64 t, %1; cvt.u32.u64 %0, t; }"
        : "=r"(a) : "l"(p));
    return a;
}
__device__ __forceinline__ uint32_t packbf(float lo, float hi) {
    uint32_t r;
    asm("cvt.rn.bf16x2.f32 %0, %1, %2;" : "=r"(r) : "f"(hi), "f"(lo));
    return r;
}
__device__ __forceinline__ void split2(float x0, float x1,
                                       uint32_t& hp, uint32_t& lp) {
    hp = packbf(x0, x1);
    float h0 = __uint_as_float(hp << 16);
    float h1 = __uint_as_float(hp & 0xffff0000u);
    lp = packbf(x0 - h0, x1 - h1);
}
__device__ __forceinline__ void mma16(float* c, const uint32_t* a, const uint32_t* b) {
    asm volatile(
        "mma.sync.aligned.m16n8k16.row.col.f32.bf16.bf16.f32 "
        "{%0,%1,%2,%3}, {%4,%5,%6,%7}, {%8,%9}, {%0,%1,%2,%3};"
        : "+f"(c[0]), "+f"(c[1]), "+f"(c[2]), "+f"(c[3])
        : "r"(a[0]), "r"(a[1]), "r"(a[2]), "r"(a[3]), "r"(b[0]), "r"(b[1]));
}
__device__ __forceinline__ void ldsm4(uint32_t* r, uint32_t a) {
    asm volatile("ldmatrix.sync.aligned.m8n8.x4.b16 {%0,%1,%2,%3}, [%4];"
        : "=r"(r[0]), "=r"(r[1]), "=r"(r[2]), "=r"(r[3]) : "r"(a));
}
__device__ __forceinline__ void ldsm4t(uint32_t* r, uint32_t a) {
    asm volatile("ldmatrix.sync.aligned.m8n8.x4.trans.b16 {%0,%1,%2,%3}, [%4];"
        : "=r"(r[0]), "=r"(r[1]), "=r"(r[2]), "=r"(r[3]) : "r"(a));
}
__device__ __forceinline__ float fexp2(float x) {
    x = fmaxf(x, -100.0f);
    float t = x + 12582912.0f;
    float f = x - (t - 12582912.0f);
    int   sc = __float_as_int(t) << 23;
    float p = 0.0013333558f;
    p = fmaf(p, f, 0.0096181291f);
    p = fmaf(p, f, 0.0555041087f);
    p = fmaf(p, f, 0.2402265069f);
    p = fmaf(p, f, 0.6931471806f);
    p = fmaf(p, f, 1.0f);
    return __int_as_float(__float_as_int(p) + sc);
}

// ---------------------------------------------------------------------------
// Kernel 0 (merged): blocks [0,144): Wc = Wa@Wt (fp32) -> bf16 h/l
//                    blocks [144, 144+3072): split X -> bf16 h/l
// ---------------------------------------------------------------------------
#define WC_BLKS  (NH * 12)           // 144 (d-chunks of 64)
#define CVT_BLKS (NB * NSEQ * HIDD / 2048)  // 3072

__global__ __launch_bounds__(256) void k_pre(const float* __restrict__ X,
                                             const float* __restrict__ Wt,
                                             const float* __restrict__ Wa) {
    if (blockIdx.x >= WC_BLKS) {
        size_t t = (size_t)(blockIdx.x - WC_BLKS) * 256 + threadIdx.x;
        float4 v0 = *(const float4*)&X[t * 8];
        float4 v1 = *(const float4*)&X[t * 8 + 4];
        uint4 hp, lp;
        split2(v0.x, v0.y, hp.x, lp.x);
        split2(v0.z, v0.w, hp.y, lp.y);
        split2(v1.x, v1.y, hp.z, lp.z);
        split2(v1.z, v1.w, hp.w, lp.w);
        *(uint4*)&g_Xh[t * 4] = hp;
        *(uint4*)&g_Xl[t * 4] = lp;
        return;
    }
    const int h  = blockIdx.x / 12;
    const int d0 = (blockIdx.x % 12) * 64;
    __shared__ float Wa_s[64 * 36];
    __shared__ float Wt_s[32 * 68];

    const int tid = threadIdx.x;
    const int te = tid / 16;
    const int td = tid % 16;

    float acc[4][4];
#pragma unroll
    for (int i = 0; i < 4; i++)
#pragma unroll
        for (int j = 0; j < 4; j++) acc[i][j] = 0.f;

    for (int l0 = 0; l0 < LR; l0 += 32) {
#pragma unroll
        for (int it = 0; it < 2; it++) {
            int f = tid + it * 256;
            int e = f / 8, l4 = f % 8;
            float4 v = *(const float4*)&Wa[((size_t)h * 64 + e) * LR + l0 + l4 * 4];
            *(float4*)&Wa_s[e * 36 + l4 * 4] = v;
        }
#pragma unroll
        for (int it = 0; it < 2; it++) {
            int f = tid + it * 256;
            int l = f / 16, c4 = f % 16;
            float4 v = *(const float4*)&Wt[((size_t)h * LR + l0 + l) * HIDD + d0 + c4 * 4];
            *(float4*)&Wt_s[l * 68 + c4 * 4] = v;
        }
        __syncthreads();
#pragma unroll
        for (int l = 0; l < 32; l++) {
            float a[4];
#pragma unroll
            for (int i = 0; i < 4; i++) a[i] = Wa_s[(te * 4 + i) * 36 + l];
            float w[4];
            *(float4*)w = *(const float4*)&Wt_s[l * 68 + td * 4];
#pragma unroll
            for (int i = 0; i < 4; i++)
#pragma unroll
                for (int j = 0; j < 4; j++) acc[i][j] = fmaf(a[i], w[j], acc[i][j]);
        }
        __syncthreads();
    }
#pragma unroll
    for (int i = 0; i < 4; i++) {
        uint32_t h0, l0u, h1, l1u;
        split2(acc[i][0], acc[i][1], h0, l0u);
        split2(acc[i][2], acc[i][3], h1, l1u);
        size_t base = ((size_t)h * HD + te * 4 + i) * (HIDD / 2) + d0 / 2 + td * 2;
        *(uint2*)&g_Wh[base] = make_uint2(h0, h1);
        *(uint2*)&g_Wl[base] = make_uint2(l0u, l1u);
    }
}

// ---------------------------------------------------------------------------
// Kernel 1: t = X * Wc^T via bf16 split 3-term mma; writes g_th/g_tl
// ---------------------------------------------------------------------------
#define PS_XH 0
#define PS_XL 2560
#define PS_WH 5120
#define PS_WL 6400
#define PS_SZ 7680
#define PROJ_SMEM_BYTES (2 * PS_SZ * 4)
#define NKIT  (HIDD / 32)

__global__ __launch_bounds__(256, 2) void k_proj_mma(int dummy) {
    extern __shared__ uint32_t su[];
    const uint32_t smb = smem_u32(su);

    const int bh = blockIdx.y, b = bh / NH, h = bh % NH;
    const int n0 = blockIdx.x * 128;
    const int tid = threadIdx.x, wid = tid >> 5, lid = tid & 31;
    const int mw = wid & 3, nw = wid >> 2;
    const int g = lid >> 2, t4 = lid & 3;
    const int mrow = mw * 32, ncol = nw * 32;

    const uint32_t* Xh = g_Xh + (size_t)(b * NSEQ + n0) * (HIDD / 2);
    const uint32_t* Xl = g_Xl + (size_t)(b * NSEQ + n0) * (HIDD / 2);
    const uint32_t* Wh = g_Wh + (size_t)h * HD * (HIDD / 2);
    const uint32_t* Wl = g_Wl + (size_t)h * HD * (HIDD / 2);

    auto issue = [&](int ki) {
        const int st = (ki & 1) * PS_SZ;
        const int k2 = ki * 16;
#pragma unroll
        for (int it = 0; it < 2; it++) {
            int f = tid + it * 256;
            int r = f >> 2, c4 = (f & 3) * 4;
            uint32_t d0 = smb + (uint32_t)(st + PS_XH + r * 20 + c4) * 4u;
            uint32_t d1 = smb + (uint32_t)(st + PS_XL + r * 20 + c4) * 4u;
            asm volatile("cp.async.cg.shared.global [%0], [%1], 16;"
                         :: "r"(d0), "l"(Xh + (size_t)r * (HIDD / 2) + k2 + c4));
            asm volatile("cp.async.cg.shared.global [%0], [%1], 16;"
                         :: "r"(d1), "l"(Xl + (size_t)r * (HIDD / 2) + k2 + c4));
        }
        {
            int r = tid >> 2, c4 = (tid & 3) * 4;
            uint32_t d0 = smb + (uint32_t)(st + PS_WH + r * 20 + c4) * 4u;
            uint32_t d1 = smb + (uint32_t)(st + PS_WL + r * 20 + c4) * 4u;
            asm volatile("cp.async.cg.shared.global [%0], [%1], 16;"
                         :: "r"(d0), "l"(Wh + (size_t)r * (HIDD / 2) + k2 + c4));
            asm volatile("cp.async.cg.shared.global [%0], [%1], 16;"
                         :: "r"(d1), "l"(Wl + (size_t)r * (HIDD / 2) + k2 + c4));
        }
        asm volatile("cp.async.commit_group;" ::: "memory");
    };

    float acc[2][4][4];
#pragma unroll
    for (int mi = 0; mi < 2; mi++)
#pragma unroll
        for (int nj = 0; nj < 4; nj++)
#pragma unroll
            for (int r = 0; r < 4; r++) acc[mi][nj][r] = 0.f;

    issue(0);
    for (int ki = 0; ki < NKIT; ki++) {
        if (ki + 1 < NKIT) {
            issue(ki + 1);
            asm volatile("cp.async.wait_group 1;" ::: "memory");
        } else {
            asm volatile("cp.async.wait_group 0;" ::: "memory");
        }
        __syncthreads();

        const uint32_t* S = su + (ki & 1) * PS_SZ;
#pragma unroll
        for (int kk = 0; kk < 2; kk++) {
            const int ko = kk * 8;
            uint32_t ah[2][4], al[2][4];
#pragma unroll
            for (int mi = 0; mi < 2; mi++) {
                int base = (mrow + mi * 16 + g) * 20 + ko + t4;
                ah[mi][0] = S[PS_XH + base];
                ah[mi][1] = S[PS_XH + base + 160];
                ah[mi][2] = S[PS_XH + base + 4];
                ah[mi][3] = S[PS_XH + base + 164];
                al[mi][0] = S[PS_XL + base];
                al[mi][1] = S[PS_XL + base + 160];
                al[mi][2] = S[PS_XL + base + 4];
                al[mi][3] = S[PS_XL + base + 164];
            }
#pragma unroll
            for (int nj = 0; nj < 4; nj++) {
                int bb = (ncol + nj * 8 + g) * 20 + ko + t4;
                uint32_t bhv[2] = { S[PS_WH + bb], S[PS_WH + bb + 4] };
                uint32_t blv[2] = { S[PS_WL + bb], S[PS_WL + bb + 4] };
#pragma unroll
                for (int mi = 0; mi < 2; mi++) {
                    mma16(acc[mi][nj], ah[mi], bhv);
                    mma16(acc[mi][nj], ah[mi], blv);
                    mma16(acc[mi][nj], al[mi], bhv);
                }
            }
        }
        __syncthreads();
    }

    uint32_t* Oh = g_th + ((size_t)bh * NSEQ + n0) * (HD / 2);
    uint32_t* Ol = g_tl + ((size_t)bh * NSEQ + n0) * (HD / 2);
#pragma unroll
    for (int mi = 0; mi < 2; mi++) {
        int r0 = mrow + mi * 16 + g;
#pragma unroll
        for (int nj = 0; nj < 4; nj++) {
            int cu = (ncol + nj * 8) / 2 + t4;
            uint32_t hp, lp;
            split2(acc[mi][nj][0], acc[mi][nj][1], hp, lp);
            Oh[(size_t)r0 * (HD / 2) + cu] = hp;
            Ol[(size_t)r0 * (HD / 2) + cu] = lp;
            split2(acc[mi][nj][2], acc[mi][nj][3], hp, lp);
            Oh[(size_t)(r0 + 8) * (HD / 2) + cu] = hp;
            Ol[(size_t)(r0 + 8) * (HD / 2) + cu] = lp;
        }
    }
}

// ---------------------------------------------------------------------------
// Kernel 2: bf16-split flash attention. Warp w owns q rows [w*16, w*16+16)
// over ALL keys -> PV B-frags are warp-local (no exchange), 1 sync/iter.
// ---------------------------------------------------------------------------
#define A_OQH 0                     // 128*144
#define A_OQL 18432
#define A_OKT 36864                 // 2 stages * (h 9216 | l 9216)
#define A_OB  73728                 // float[2][64]
#define A_OL  74240                 // float[128]
#define A_SM  74752

#define CE 0.052058774f             // 768^-0.5 * log2(e)

__global__ __launch_bounds__(256, 2) void k_attn5(const int* __restrict__ amask,
                                                  float* __restrict__ out) {
    extern __shared__ __align__(128) char smem[];
    const uint32_t smb = smem_u32(smem);

    const int bh = blockIdx.y, b = bh / NH, h = bh % NH;
    const int q0 = blockIdx.x * QT;
    const int tid = threadIdx.x, wid = tid >> 5, lid = tid & 31;
    const int g = lid >> 2, t4 = lid & 3;
    const int w16 = wid * 16;
    const int lane7 = lid & 7;
    const int lane8 = (lid & 8) ? 8 : 0;
    const int lane16 = (lid & 16) ? 8 : 0;

    const uint32_t* Th = g_th + (size_t)bh * NSEQ * (HD / 2);
    const uint32_t* Tl = g_tl + (size_t)bh * NSEQ * (HD / 2);
    const int* mb = amask + (size_t)b * NSEQ;
    float* biasf = (float*)(smem + A_OB);

    // prologue: Q (hi+lo), K tile 0, bias 0
#pragma unroll
    for (int it = 0; it < 8; it++) {
        int f = tid + it * 256;
        int cp = f >> 10, r = (f >> 3) & 127, c = f & 7;
        uint32_t dst = smb + (cp ? A_OQL : A_OQH) + (uint32_t)(r * 144 + c * 16);
        const uint32_t* src = (cp ? Tl : Th) + (size_t)(q0 + r) * 32 + c * 4;
        asm volatile("cp.async.cg.shared.global [%0], [%1], 16;"
                     :: "r"(dst), "l"(src));
    }
#pragma unroll
    for (int it = 0; it < 4; it++) {
        int f = tid + it * 256;
        int cp = f >> 9, r = (f >> 3) & 63, c = f & 7;
        uint32_t dst = smb + A_OKT + cp * 9216 + (uint32_t)(r * 144 + c * 16);
        const uint32_t* src = (cp ? Tl : Th) + (size_t)r * 32 + c * 4;
        asm volatile("cp.async.cg.shared.global [%0], [%1], 16;"
                     :: "r"(dst), "l"(src));
    }
    asm volatile("cp.async.commit_group;" ::: "memory");
    if (tid < 64) biasf[tid] = (mb[tid] == 0) ? -3000.f : -12.f;

    float rs0 = 0.f, rs1 = 0.f;
    float oacc[4][2][4];
#pragma unroll
    for (int me = 0; me < 4; me++)
#pragma unroll
        for (int n = 0; n < 2; n++)
#pragma unroll
            for (int r = 0; r < 4; r++) oacc[me][n][r] = 0.f;

    const uint32_t roq_base = smb + (uint32_t)((w16 + lane7 + lane8) * 144
                                               + lane16 * 2);
    const uint32_t rok_off  = (uint32_t)((lane7 + lane16) * 144 + lane8 * 2);

#pragma unroll 1
    for (int i = 0; i < NIT; i++) {
        asm volatile("cp.async.wait_group 0;" ::: "memory");
        __syncthreads();

        // prefetch next K tile + bias
        if (i + 1 < NIT) {
            int j0 = (i + 1) * KT;
#pragma unroll
            for (int it = 0; it < 4; it++) {
                int f = tid + it * 256;
                int cp = f >> 9, r = (f >> 3) & 63, c = f & 7;
                uint32_t dst = smb + A_OKT + ((i + 1) & 1) * 18432 + cp * 9216
                             + (uint32_t)(r * 144 + c * 16);
                const uint32_t* src = (cp ? Tl : Th) + (size_t)(j0 + r) * 32 + c * 4;
                asm volatile("cp.async.cg.shared.global [%0], [%1], 16;"
                             :: "r"(dst), "l"(src));
            }
            asm volatile("cp.async.commit_group;" ::: "memory");
            if (tid < 64)
                biasf[((i + 1) & 1) * 64 + tid] =
                    (mb[j0 + tid] == 0) ? -3000.f : -12.f;
        }

        const uint32_t khb = smb + A_OKT + (i & 1) * 18432;
        const uint32_t klb = khb + 9216;

        // ---- S = Q K^T, 3-term bf16 (16q x 64key) ----
        float sacc[8][4];
#pragma unroll
        for (int nj = 0; nj < 8; nj++)
#pragma unroll
            for (int r = 0; r < 4; r++) sacc[nj][r] = 0.f;

#pragma unroll
        for (int kb = 0; kb < 4; kb++) {
            uint32_t qh[4], ql[4];
            ldsm4(qh, (A_OQH - A_OQH) + roq_base + kb * 32);       // A_OQH base
            ldsm4(ql, roq_base + (A_OQL - A_OQH) + kb * 32);
#pragma unroll
            for (int kt = 0; kt < 4; kt++) {
                uint32_t kh[4], kl[4];
                uint32_t rok = (uint32_t)(kt * 16 * 144 + kb * 32) + rok_off;
                ldsm4(kh, khb + rok);
                ldsm4(kl, klb + rok);
#pragma unroll
                for (int j = 0; j < 2; j++) {
                    uint32_t bh2[2] = { kh[j * 2], kh[j * 2 + 1] };
                    uint32_t bl2[2] = { kl[j * 2], kl[j * 2 + 1] };
                    float* c = sacc[kt * 2 + j];
                    mma16(c, qh, bh2);
                    mma16(c, ql, bh2);
                    mma16(c, qh, bl2);
                }
            }
        }

        // ---- exp2 (static bias) -> packed bf16 PV B-frags (registers) ----
        uint32_t u01[8], u23[8];
        const float* bi = biasf + (i & 1) * 64;
#pragma unroll
        for (int nj = 0; nj < 8; nj++) {
            float bx = bi[nj * 8 + 2 * t4];
            float by = bi[nj * 8 + 2 * t4 + 1];
            float* c = sacc[nj];
            float p0 = fexp2(fmaf(c[0], CE, bx));
            float p1 = fexp2(fmaf(c[1], CE, by));
            float p2 = fexp2(fmaf(c[2], CE, bx));
            float p3 = fexp2(fmaf(c[3], CE, by));
            uint32_t a = packbf(p0, p1);
            uint32_t b2 = packbf(p2, p3);
            u01[nj] = a; u23[nj] = b2;
            rs0 += __uint_as_float(a << 16) + __uint_as_float(a & 0xffff0000u);
            rs1 += __uint_as_float(b2 << 16) + __uint_as_float(b2 & 0xffff0000u);
        }

        // ---- O^T += V^T P^T (all frags warp-local) ----
#pragma unroll
        for (int kt = 0; kt < 4; kt++) {
            uint32_t b0[2] = { u01[kt * 2], u01[kt * 2 + 1] };
            uint32_t b1[2] = { u23[kt * 2], u23[kt * 2 + 1] };
#pragma unroll
            for (int me = 0; me < 4; me++) {
                uint32_t rov = (uint32_t)((kt * 16 + lane7 + lane16) * 144
                                          + (me * 16 + lane8) * 2);
                uint32_t ah[4], al[4];
                ldsm4t(ah, khb + rov);
                ldsm4t(al, klb + rov);
                mma16(oacc[me][0], ah, b0);
                mma16(oacc[me][0], al, b0);
                mma16(oacc[me][1], ah, b1);
                mma16(oacc[me][1], al, b1);
            }
        }
    }

    // ---- epilogue: warp-local l, normalize, write ----
    rs0 += __shfl_xor_sync(0xffffffffu, rs0, 1);
    rs0 += __shfl_xor_sync(0xffffffffu, rs0, 2);
    rs1 += __shfl_xor_sync(0xffffffffu, rs1, 1);
    rs1 += __shfl_xor_sync(0xffffffffu, rs1, 2);
    float* lred = (float*)(smem + A_OL);
    if (t4 == 0) {
        lred[w16 + g] = rs0;
        lred[w16 + 8 + g] = rs1;
    }
    __syncthreads();

    const int qa = w16 + 2 * t4;
    const float inv0 = 1.f / lred[qa];
    const float inv1 = 1.f / lred[qa + 1];
    const float inv2 = 1.f / lred[qa + 8];
    const float inv3 = 1.f / lred[qa + 9];
    float* ob = out + ((size_t)b * NSEQ + q0 + qa) * (NH * HD) + h * HD;
#pragma unroll
    for (int me = 0; me < 4; me++) {
        int e0 = me * 16 + g;
        ob[e0]                        = oacc[me][0][0] * inv0;
        ob[NH * HD + e0]              = oacc[me][0][1] * inv1;
        ob[e0 + 8]                    = oacc[me][0][2] * inv0;
        ob[NH * HD + e0 + 8]          = oacc[me][0][3] * inv1;
        ob[8 * NH * HD + e0]          = oacc[me][1][0] * inv2;
        ob[9 * NH * HD + e0]          = oacc[me][1][1] * inv3;
        ob[8 * NH * HD + e0 + 8]      = oacc[me][1][2] * inv2;
        ob[9 * NH * HD + e0 + 8]      = oacc[me][1][3] * inv3;
    }
}

// ---------------------------------------------------------------------------
extern "C" void kernel_launch(void* const* d_in, const int* in_sizes, int n_in,
                              void* d_out, int out_size) {
    const float* hidden = (const float*)d_in[0];
    const int*   amask  = (const int*)d_in[1];
    const float* Wt     = (const float*)d_in[2];
    const float* Wa     = (const float*)d_in[3];
    float* out = (float*)d_out;

    k_pre<<<WC_BLKS + CVT_BLKS, 256>>>(hidden, Wt, Wa);

    cudaFuncSetAttribute(k_proj_mma, cudaFuncAttributeMaxDynamicSharedMemorySize,
                         PROJ_SMEM_BYTES);
    k_proj_mma<<<dim3(NSEQ / 128, NB * NH), 256, PROJ_SMEM_BYTES>>>(0);

    cudaFuncSetAttribute(k_attn5, cudaFuncAttributeMaxDynamicSharedMemorySize,
                         A_SM);
    k_attn5<<<dim3(NSEQ / QT, NB * NH), 256, A_SM>>>(amask, out);
}

// round 8
// speedup vs baseline: 3.4284x; 1.1225x over previous
#include <cuda_runtime.h>
#include <cuda_bf16.h>
#include <cuda_fp16.h>
#include <cstdint>

#define NB    8
#define NSEQ  1024
#define HIDD  768
#define NH    12
#define LR    256
#define HD    64

#define QT    128
#define KT    64
#define NIT   (NSEQ / KT)

// scratch (no cudaMalloc allowed)
__device__ uint32_t g_Xh[NB * NSEQ * (HIDD / 2)];    // X bf16 hi, k-pair packed
__device__ uint32_t g_Xl[NB * NSEQ * (HIDD / 2)];
__device__ uint32_t g_Wh[NH * HD * (HIDD / 2)];      // Wc bf16 hi
__device__ uint32_t g_Wl[NH * HD * (HIDD / 2)];
__device__ float    g_t  [NB * NH * NSEQ * HD];      // t fp32 (Q,K source)
__device__ uint32_t g_t16[NB * NH * NSEQ * (HD / 2)];// t fp16 e-pairs (V source)

// ---------------------------------------------------------------------------
// helpers
// ---------------------------------------------------------------------------
__device__ __forceinline__ uint32_t smem_u32(const void* p) {
    uint32_t a;
    asm("{ .reg .u64 t; cvta.to.shared.u64 t, %1; cvt.u32.u64 %0, t; }"
        : "=r"(a) : "l"(p));
    return a;
}
__device__ __forceinline__ uint32_t packbf(float lo, float hi) {
    uint32_t r;
    asm("cvt.rn.bf16x2.f32 %0, %1, %2;" : "=r"(r) : "f"(hi), "f"(lo));
    return r;
}
__device__ __forceinline__ uint32_t packf16(float lo, float hi) {
    uint32_t r;
    asm("cvt.rn.f16x2.f32 %0, %1, %2;" : "=r"(r) : "f"(hi), "f"(lo));
    return r;
}
__device__ __forceinline__ void split2(float x0, float x1,
                                       uint32_t& hp, uint32_t& lp) {
    hp = packbf(x0, x1);
    float h0 = __uint_as_float(hp << 16);
    float h1 = __uint_as_float(hp & 0xffff0000u);
    lp = packbf(x0 - h0, x1 - h1);
}
// tf32 m16n8k8 (attention S)
__device__ __forceinline__ void mma8(float* c, const uint32_t* a, const uint32_t* b) {
    asm volatile(
        "mma.sync.aligned.m16n8k8.row.col.f32.tf32.tf32.f32 "
        "{%0,%1,%2,%3}, {%4,%5,%6,%7}, {%8,%9}, {%0,%1,%2,%3};"
        : "+f"(c[0]), "+f"(c[1]), "+f"(c[2]), "+f"(c[3])
        : "r"(a[0]), "r"(a[1]), "r"(a[2]), "r"(a[3]), "r"(b[0]), "r"(b[1]));
}
// bf16 m16n8k16 (projection)
__device__ __forceinline__ void mma16(float* c, const uint32_t* a, const uint32_t* b) {
    asm volatile(
        "mma.sync.aligned.m16n8k16.row.col.f32.bf16.bf16.f32 "
        "{%0,%1,%2,%3}, {%4,%5,%6,%7}, {%8,%9}, {%0,%1,%2,%3};"
        : "+f"(c[0]), "+f"(c[1]), "+f"(c[2]), "+f"(c[3])
        : "r"(a[0]), "r"(a[1]), "r"(a[2]), "r"(a[3]), "r"(b[0]), "r"(b[1]));
}
// fp16 m16n8k16 (attention PV)
__device__ __forceinline__ void mma16h(float* c, const uint32_t* a, const uint32_t* b) {
    asm volatile(
        "mma.sync.aligned.m16n8k16.row.col.f32.f16.f16.f32 "
        "{%0,%1,%2,%3}, {%4,%5,%6,%7}, {%8,%9}, {%0,%1,%2,%3};"
        : "+f"(c[0]), "+f"(c[1]), "+f"(c[2]), "+f"(c[3])
        : "r"(a[0]), "r"(a[1]), "r"(a[2]), "r"(a[3]), "r"(b[0]), "r"(b[1]));
}
__device__ __forceinline__ void ldsm4(uint32_t* r, uint32_t a) {
    asm volatile("ldmatrix.sync.aligned.m8n8.x4.b16 {%0,%1,%2,%3}, [%4];"
        : "=r"(r[0]), "=r"(r[1]), "=r"(r[2]), "=r"(r[3]) : "r"(a));
}
__device__ __forceinline__ void ldsm4t(uint32_t* r, uint32_t a) {
    asm volatile("ldmatrix.sync.aligned.m8n8.x4.trans.b16 {%0,%1,%2,%3}, [%4];"
        : "=r"(r[0]), "=r"(r[1]), "=r"(r[2]), "=r"(r[3]) : "r"(a));
}
__device__ __forceinline__ float fexp2(float x) {
    x = fmaxf(x, -100.0f);
    float t = x + 12582912.0f;
    float f = x - (t - 12582912.0f);
    int   sc = __float_as_int(t) << 23;
    float p = 0.0013333558f;
    p = fmaf(p, f, 0.0096181291f);
    p = fmaf(p, f, 0.0555041087f);
    p = fmaf(p, f, 0.2402265069f);
    p = fmaf(p, f, 0.6931471806f);
    p = fmaf(p, f, 1.0f);
    return __int_as_float(__float_as_int(p) + sc);
}

// ---------------------------------------------------------------------------
// Kernel 0 (merged): blocks [0,144): Wc = Wa@Wt (fp32) -> bf16 h/l
//                    blocks [144, 144+3072): split X -> bf16 h/l
// ---------------------------------------------------------------------------
#define WC_BLKS  (NH * 12)
#define CVT_BLKS (NB * NSEQ * HIDD / 2048)

__global__ __launch_bounds__(256) void k_pre(const float* __restrict__ X,
                                             const float* __restrict__ Wt,
                                             const float* __restrict__ Wa) {
    if (blockIdx.x >= WC_BLKS) {
        size_t t = (size_t)(blockIdx.x - WC_BLKS) * 256 + threadIdx.x;
        float4 v0 = *(const float4*)&X[t * 8];
        float4 v1 = *(const float4*)&X[t * 8 + 4];
        uint4 hp, lp;
        split2(v0.x, v0.y, hp.x, lp.x);
        split2(v0.z, v0.w, hp.y, lp.y);
        split2(v1.x, v1.y, hp.z, lp.z);
        split2(v1.z, v1.w, hp.w, lp.w);
        *(uint4*)&g_Xh[t * 4] = hp;
        *(uint4*)&g_Xl[t * 4] = lp;
        return;
    }
    const int h  = blockIdx.x / 12;
    const int d0 = (blockIdx.x % 12) * 64;
    __shared__ float Wa_s[64 * 36];
    __shared__ float Wt_s[32 * 68];

    const int tid = threadIdx.x;
    const int te = tid / 16;
    const int td = tid % 16;

    float acc[4][4];
#pragma unroll
    for (int i = 0; i < 4; i++)
#pragma unroll
        for (int j = 0; j < 4; j++) acc[i][j] = 0.f;

    for (int l0 = 0; l0 < LR; l0 += 32) {
#pragma unroll
        for (int it = 0; it < 2; it++) {
            int f = tid + it * 256;
            int e = f / 8, l4 = f % 8;
            float4 v = *(const float4*)&Wa[((size_t)h * 64 + e) * LR + l0 + l4 * 4];
            *(float4*)&Wa_s[e * 36 + l4 * 4] = v;
        }
#pragma unroll
        for (int it = 0; it < 2; it++) {
            int f = tid + it * 256;
            int l = f / 16, c4 = f % 16;
            float4 v = *(const float4*)&Wt[((size_t)h * LR + l0 + l) * HIDD + d0 + c4 * 4];
            *(float4*)&Wt_s[l * 68 + c4 * 4] = v;
        }
        __syncthreads();
#pragma unroll
        for (int l = 0; l < 32; l++) {
            float a[4];
#pragma unroll
            for (int i = 0; i < 4; i++) a[i] = Wa_s[(te * 4 + i) * 36 + l];
            float w[4];
            *(float4*)w = *(const float4*)&Wt_s[l * 68 + td * 4];
#pragma unroll
            for (int i = 0; i < 4; i++)
#pragma unroll
                for (int j = 0; j < 4; j++) acc[i][j] = fmaf(a[i], w[j], acc[i][j]);
        }
        __syncthreads();
    }
#pragma unroll
    for (int i = 0; i < 4; i++) {
        uint32_t h0, l0u, h1, l1u;
        split2(acc[i][0], acc[i][1], h0, l0u);
        split2(acc[i][2], acc[i][3], h1, l1u);
        size_t base = ((size_t)h * HD + te * 4 + i) * (HIDD / 2) + d0 / 2 + td * 2;
        *(uint2*)&g_Wh[base] = make_uint2(h0, h1);
        *(uint2*)&g_Wl[base] = make_uint2(l0u, l1u);
    }
}

// ---------------------------------------------------------------------------
// Kernel 1: t = X * Wc^T via bf16 split 3-term mma; writes fp32 + fp16 t
// ---------------------------------------------------------------------------
#define PS_XH 0
#define PS_XL 2560
#define PS_WH 5120
#define PS_WL 6400
#define PS_SZ 7680
#define PROJ_SMEM_BYTES (2 * PS_SZ * 4)
#define NKIT  (HIDD / 32)

__global__ __launch_bounds__(256, 2) void k_proj_mma(int dummy) {
    extern __shared__ uint32_t su[];
    const uint32_t smb = smem_u32(su);

    const int bh = blockIdx.y, b = bh / NH, h = bh % NH;
    const int n0 = blockIdx.x * 128;
    const int tid = threadIdx.x, wid = tid >> 5, lid = tid & 31;
    const int mw = wid & 3, nw = wid >> 2;
    const int g = lid >> 2, t4 = lid & 3;
    const int mrow = mw * 32, ncol = nw * 32;

    const uint32_t* Xh = g_Xh + (size_t)(b * NSEQ + n0) * (HIDD / 2);
    const uint32_t* Xl = g_Xl + (size_t)(b * NSEQ + n0) * (HIDD / 2);
    const uint32_t* Wh = g_Wh + (size_t)h * HD * (HIDD / 2);
    const uint32_t* Wl = g_Wl + (size_t)h * HD * (HIDD / 2);

    auto issue = [&](int ki) {
        const int st = (ki & 1) * PS_SZ;
        const int k2 = ki * 16;
#pragma unroll
        for (int it = 0; it < 2; it++) {
            int f = tid + it * 256;
            int r = f >> 2, c4 = (f & 3) * 4;
            uint32_t d0 = smb + (uint32_t)(st + PS_XH + r * 20 + c4) * 4u;
            uint32_t d1 = smb + (uint32_t)(st + PS_XL + r * 20 + c4) * 4u;
            asm volatile("cp.async.cg.shared.global [%0], [%1], 16;"
                         :: "r"(d0), "l"(Xh + (size_t)r * (HIDD / 2) + k2 + c4));
            asm volatile("cp.async.cg.shared.global [%0], [%1], 16;"
                         :: "r"(d1), "l"(Xl + (size_t)r * (HIDD / 2) + k2 + c4));
        }
        {
            int r = tid >> 2, c4 = (tid & 3) * 4;
            uint32_t d0 = smb + (uint32_t)(st + PS_WH + r * 20 + c4) * 4u;
            uint32_t d1 = smb + (uint32_t)(st + PS_WL + r * 20 + c4) * 4u;
            asm volatile("cp.async.cg.shared.global [%0], [%1], 16;"
                         :: "r"(d0), "l"(Wh + (size_t)r * (HIDD / 2) + k2 + c4));
            asm volatile("cp.async.cg.shared.global [%0], [%1], 16;"
                         :: "r"(d1), "l"(Wl + (size_t)r * (HIDD / 2) + k2 + c4));
        }
        asm volatile("cp.async.commit_group;" ::: "memory");
    };

    float acc[2][4][4];
#pragma unroll
    for (int mi = 0; mi < 2; mi++)
#pragma unroll
        for (int nj = 0; nj < 4; nj++)
#pragma unroll
            for (int r = 0; r < 4; r++) acc[mi][nj][r] = 0.f;

    issue(0);
    for (int ki = 0; ki < NKIT; ki++) {
        if (ki + 1 < NKIT) {
            issue(ki + 1);
            asm volatile("cp.async.wait_group 1;" ::: "memory");
        } else {
            asm volatile("cp.async.wait_group 0;" ::: "memory");
        }
        __syncthreads();

        const uint32_t* S = su + (ki & 1) * PS_SZ;
#pragma unroll
        for (int kk = 0; kk < 2; kk++) {
            const int ko = kk * 8;
            uint32_t ah[2][4], al[2][4];
#pragma unroll
            for (int mi = 0; mi < 2; mi++) {
                int base = (mrow + mi * 16 + g) * 20 + ko + t4;
                ah[mi][0] = S[PS_XH + base];
                ah[mi][1] = S[PS_XH + base + 160];
                ah[mi][2] = S[PS_XH + base + 4];
                ah[mi][3] = S[PS_XH + base + 164];
                al[mi][0] = S[PS_XL + base];
                al[mi][1] = S[PS_XL + base + 160];
                al[mi][2] = S[PS_XL + base + 4];
                al[mi][3] = S[PS_XL + base + 164];
            }
#pragma unroll
            for (int nj = 0; nj < 4; nj++) {
                int bb = (ncol + nj * 8 + g) * 20 + ko + t4;
                uint32_t bhv[2] = { S[PS_WH + bb], S[PS_WH + bb + 4] };
                uint32_t blv[2] = { S[PS_WL + bb], S[PS_WL + bb + 4] };
#pragma unroll
                for (int mi = 0; mi < 2; mi++) {
                    mma16(acc[mi][nj], ah[mi], bhv);
                    mma16(acc[mi][nj], ah[mi], blv);
                    mma16(acc[mi][nj], al[mi], bhv);
                }
            }
        }
        __syncthreads();
    }

    // epilogue: fp32 t + fp16 t
    float*    Tf  = g_t   + ((size_t)bh * NSEQ + n0) * HD;
    uint32_t* T16 = g_t16 + ((size_t)bh * NSEQ + n0) * (HD / 2);
#pragma unroll
    for (int mi = 0; mi < 2; mi++) {
        int r0 = mrow + mi * 16 + g;
#pragma unroll
        for (int nj = 0; nj < 4; nj++) {
            int c = ncol + nj * 8 + 2 * t4;
            *(float2*)&Tf[(size_t)r0 * HD + c] =
                make_float2(acc[mi][nj][0], acc[mi][nj][1]);
            *(float2*)&Tf[(size_t)(r0 + 8) * HD + c] =
                make_float2(acc[mi][nj][2], acc[mi][nj][3]);
            T16[(size_t)r0 * (HD / 2) + (c >> 1)] =
                packf16(acc[mi][nj][0], acc[mi][nj][1]);
            T16[(size_t)(r0 + 8) * (HD / 2) + (c >> 1)] =
                packf16(acc[mi][nj][2], acc[mi][nj][3]);
        }
    }
}

// ---------------------------------------------------------------------------
// Kernel 2: flash attention. S: tf32 m16n8k8 single-term (Q,K fp32 in smem,
// frags via ldmatrix on fp32). PV: fp16 single-term, P from C->B identity.
// Warp w owns q rows [w*16, w*16+16) over ALL keys. 1 sync/iter.
// ---------------------------------------------------------------------------
#define A_QF   0                    // 128 * 272 fp32
#define A_KF   34816                // 2 stages * 64*272
#define A_KSTG 17408
#define A_VH   69632                // 2 stages * 64*144 fp16
#define A_VSTG 9216
#define A_OB   88064                // float[2][64]
#define A_OL   88576                // float[128]
#define A_SM   89088

#define CE 0.052058774f             // 768^-0.5 * log2(e)

__global__ __launch_bounds__(256, 2) void k_attn6(const int* __restrict__ amask,
                                                  float* __restrict__ out) {
    extern __shared__ __align__(128) char smem[];
    const uint32_t smb = smem_u32(smem);

    const int bh = blockIdx.y, b = bh / NH, h = bh % NH;
    const int q0 = blockIdx.x * QT;
    const int tid = threadIdx.x, wid = tid >> 5, lid = tid & 31;
    const int g = lid >> 2, t4 = lid & 3;
    const int w16 = wid * 16;
    const int l7 = lid & 7;
    const int r8  = (lid & 8)  ? 8 : 0;
    const int r16 = (lid & 16) ? 8 : 0;

    const float*    Tf  = g_t   + (size_t)bh * NSEQ * HD;
    const uint32_t* T16 = g_t16 + (size_t)bh * NSEQ * (HD / 2);
    const int* mb = amask + (size_t)b * NSEQ;
    float* biasf = (float*)(smem + A_OB);

    // prologue: Q fp32 (32KB), K tile 0 fp32, V tile 0 fp16, bias 0
#pragma unroll
    for (int it = 0; it < 8; it++) {
        int f = tid + it * 256;
        int r = f >> 4, c = f & 15;
        uint32_t dst = smb + A_QF + (uint32_t)(r * 272 + c * 16);
        asm volatile("cp.async.cg.shared.global [%0], [%1], 16;"
                     :: "r"(dst), "l"(Tf + (size_t)(q0 + r) * HD + c * 4));
    }
#pragma unroll
    for (int it = 0; it < 4; it++) {
        int f = tid + it * 256;
        int r = f >> 4, c = f & 15;
        uint32_t dst = smb + A_KF + (uint32_t)(r * 272 + c * 16);
        asm volatile("cp.async.cg.shared.global [%0], [%1], 16;"
                     :: "r"(dst), "l"(Tf + (size_t)r * HD + c * 4));
    }
#pragma unroll
    for (int it = 0; it < 2; it++) {
        int f = tid + it * 256;
        int r = f >> 3, c = f & 7;
        uint32_t dst = smb + A_VH + (uint32_t)(r * 144 + c * 16);
        asm volatile("cp.async.cg.shared.global [%0], [%1], 16;"
                     :: "r"(dst), "l"(T16 + (size_t)r * (HD / 2) + c * 4));
    }
    asm volatile("cp.async.commit_group;" ::: "memory");
    if (tid < 64) biasf[tid] = (mb[tid] == 0) ? -3000.f : 0.f;

    float rs0 = 0.f, rs1 = 0.f;
    float oacc[4][2][4];
#pragma unroll
    for (int me = 0; me < 4; me++)
#pragma unroll
        for (int n = 0; n < 2; n++)
#pragma unroll
            for (int r = 0; r < 4; r++) oacc[me][n][r] = 0.f;

    // lane-dependent ldmatrix offsets
    const uint32_t qro = (uint32_t)((w16 + l7 + r8) * 272 + ((lid & 16) ? 16 : 0));
    const uint32_t kro = (uint32_t)((l7 + r16) * 272 + ((lid & 8) ? 16 : 0));

#pragma unroll 1
    for (int i = 0; i < NIT; i++) {
        asm volatile("cp.async.wait_group 0;" ::: "memory");
        __syncthreads();

        if (i + 1 < NIT) {
            int j0 = (i + 1) * KT;
            uint32_t kst = A_KF + ((i + 1) & 1) * A_KSTG;
            uint32_t vst = A_VH + ((i + 1) & 1) * A_VSTG;
#pragma unroll
            for (int it = 0; it < 4; it++) {
                int f = tid + it * 256;
                int r = f >> 4, c = f & 15;
                uint32_t dst = smb + kst + (uint32_t)(r * 272 + c * 16);
                asm volatile("cp.async.cg.shared.global [%0], [%1], 16;"
                             :: "r"(dst), "l"(Tf + (size_t)(j0 + r) * HD + c * 4));
            }
#pragma unroll
            for (int it = 0; it < 2; it++) {
                int f = tid + it * 256;
                int r = f >> 3, c = f & 7;
                uint32_t dst = smb + vst + (uint32_t)(r * 144 + c * 16);
                asm volatile("cp.async.cg.shared.global [%0], [%1], 16;"
                             :: "r"(dst), "l"(T16 + (size_t)(j0 + r) * (HD / 2) + c * 4));
            }
            asm volatile("cp.async.commit_group;" ::: "memory");
            if (tid < 64)
                biasf[((i + 1) & 1) * 64 + tid] =
                    (mb[j0 + tid] == 0) ? -3000.f : 0.f;
        }

        const uint32_t kfb = smb + A_KF + (i & 1) * A_KSTG;
        const uint32_t vfb = smb + A_VH + (i & 1) * A_VSTG;

        // ---- S = Q K^T (tf32, single term): 16q x 64key ----
        float sacc[8][4];
#pragma unroll
        for (int kg = 0; kg < 8; kg++)
#pragma unroll
            for (int r = 0; r < 4; r++) sacc[kg][r] = 0.f;

#pragma unroll
        for (int k8 = 0; k8 < 8; k8++) {
            uint32_t qf[4];
            ldsm4(qf, smb + A_QF + qro + k8 * 32);
#pragma unroll
            for (int kgp = 0; kgp < 4; kgp++) {
                uint32_t kf[4];
                ldsm4(kf, kfb + kgp * 4352 + k8 * 32 + kro);
                mma8(sacc[2 * kgp],     qf, kf);
                mma8(sacc[2 * kgp + 1], qf, kf + 2);
            }
        }

        // ---- exp2 (masked bias) -> packed fp16 PV B-frags (registers) ----
        uint32_t u01[8], u23[8];
        const float* bi = biasf + (i & 1) * 64;
#pragma unroll
        for (int kg = 0; kg < 8; kg++) {
            float bx = bi[kg * 8 + 2 * t4];
            float by = bi[kg * 8 + 2 * t4 + 1];
            float* c = sacc[kg];
            float p0 = fexp2(fmaf(c[0], CE, bx));
            float p1 = fexp2(fmaf(c[1], CE, by));
            float p2 = fexp2(fmaf(c[2], CE, bx));
            float p3 = fexp2(fmaf(c[3], CE, by));
            rs0 += p0 + p1;
            rs1 += p2 + p3;
            u01[kg] = packf16(p0, p1);
            u23[kg] = packf16(p2, p3);
        }

        // ---- O^T += V^T P^T (fp16 single term, frags warp-local) ----
#pragma unroll
        for (int kt = 0; kt < 4; kt++) {
            uint32_t b0[2] = { u01[kt * 2], u01[kt * 2 + 1] };
            uint32_t b1[2] = { u23[kt * 2], u23[kt * 2 + 1] };
#pragma unroll
            for (int me = 0; me < 4; me++) {
                uint32_t ah[4];
                ldsm4t(ah, vfb + (uint32_t)((kt * 16 + l7 + r16) * 144
                                            + (me * 16 + r8) * 2));
                mma16h(oacc[me][0], ah, b0);
                mma16h(oacc[me][1], ah, b1);
            }
        }
    }

    // ---- epilogue ----
    rs0 += __shfl_xor_sync(0xffffffffu, rs0, 1);
    rs0 += __shfl_xor_sync(0xffffffffu, rs0, 2);
    rs1 += __shfl_xor_sync(0xffffffffu, rs1, 1);
    rs1 += __shfl_xor_sync(0xffffffffu, rs1, 2);
    float* lred = (float*)(smem + A_OL);
    if (t4 == 0) {
        lred[w16 + g] = rs0;
        lred[w16 + 8 + g] = rs1;
    }
    __syncthreads();

    const int qa = w16 + 2 * t4;
    const float inv0 = 1.f / lred[qa];
    const float inv1 = 1.f / lred[qa + 1];
    const float inv2 = 1.f / lred[qa + 8];
    const float inv3 = 1.f / lred[qa + 9];
    float* ob = out + ((size_t)b * NSEQ + q0 + qa) * (NH * HD) + h * HD;
#pragma unroll
    for (int me = 0; me < 4; me++) {
        int e0 = me * 16 + g;
        ob[e0]                   = oacc[me][0][0] * inv0;
        ob[NH * HD + e0]         = oacc[me][0][1] * inv1;
        ob[e0 + 8]               = oacc[me][0][2] * inv0;
        ob[NH * HD + e0 + 8]     = oacc[me][0][3] * inv1;
        ob[8 * NH * HD + e0]     = oacc[me][1][0] * inv2;
        ob[9 * NH * HD + e0]     = oacc[me][1][1] * inv3;
        ob[8 * NH * HD + e0 + 8] = oacc[me][1][2] * inv2;
        ob[9 * NH * HD + e0 + 8] = oacc[me][1][3] * inv3;
    }
}

// ---------------------------------------------------------------------------
extern "C" void kernel_launch(void* const* d_in, const int* in_sizes, int n_in,
                              void* d_out, int out_size) {
    const float* hidden = (const float*)d_in[0];
    const int*   amask  = (const int*)d_in[1];
    const float* Wt     = (const float*)d_in[2];
    const float* Wa     = (const float*)d_in[3];
    float* out = (float*)d_out;

    k_pre<<<WC_BLKS + CVT_BLKS, 256>>>(hidden, Wt, Wa);

    cudaFuncSetAttribute(k_proj_mma, cudaFuncAttributeMaxDynamicSharedMemorySize,
                         PROJ_SMEM_BYTES);
    k_proj_mma<<<dim3(NSEQ / 128, NB * NH), 256, PROJ_SMEM_BYTES>>>(0);

    cudaFuncSetAttribute(k_attn6, cudaFuncAttributeMaxDynamicSharedMemorySize,
                         A_SM);
    k_attn6<<<dim3(NSEQ / QT, NB * NH), 256, A_SM>>>(amask, out);
}

// round 9
// speedup vs baseline: 4.1282x; 1.2041x over previous
#include <cuda_runtime.h>
#include <cuda_bf16.h>
#include <cuda_fp16.h>
#include <cstdint>

#define NB    8
#define NSEQ  1024
#define HIDD  768
#define NH    12
#define LR    256
#define HD    64

#define QT    128
#define KT    64
#define NIT   (NSEQ / KT)

// scratch (no cudaMalloc allowed)
__device__ uint32_t g_Xh[NB * NSEQ * (HIDD / 2)];    // X bf16 hi, k-pair packed
__device__ uint32_t g_Xl[NB * NSEQ * (HIDD / 2)];
__device__ uint32_t g_Wh[NH * HD * (HIDD / 2)];      // Wc bf16 hi
__device__ uint32_t g_Wl[NH * HD * (HIDD / 2)];
__device__ uint32_t g_t16[NB * NH * NSEQ * (HD / 2)];// t fp16 e-pairs (q=k=v)

// ---------------------------------------------------------------------------
// helpers
// ---------------------------------------------------------------------------
__device__ __forceinline__ uint32_t smem_u32(const void* p) {
    uint32_t a;
    asm("{ .reg .u64 t; cvta.to.shared.u64 t, %1; cvt.u32.u64 %0, t; }"
        : "=r"(a) : "l"(p));
    return a;
}
__device__ __forceinline__ uint32_t packbf(float lo, float hi) {
    uint32_t r;
    asm("cvt.rn.bf16x2.f32 %0, %1, %2;" : "=r"(r) : "f"(hi), "f"(lo));
    return r;
}
__device__ __forceinline__ uint32_t packf16(float lo, float hi) {
    uint32_t r;
    asm("cvt.rn.f16x2.f32 %0, %1, %2;" : "=r"(r) : "f"(hi), "f"(lo));
    return r;
}
__device__ __forceinline__ void split2(float x0, float x1,
                                       uint32_t& hp, uint32_t& lp) {
    hp = packbf(x0, x1);
    float h0 = __uint_as_float(hp << 16);
    float h1 = __uint_as_float(hp & 0xffff0000u);
    lp = packbf(x0 - h0, x1 - h1);
}
// bf16 m16n8k16 (projection)
__device__ __forceinline__ void mma16(float* c, const uint32_t* a, const uint32_t* b) {
    asm volatile(
        "mma.sync.aligned.m16n8k16.row.col.f32.bf16.bf16.f32 "
        "{%0,%1,%2,%3}, {%4,%5,%6,%7}, {%8,%9}, {%0,%1,%2,%3};"
        : "+f"(c[0]), "+f"(c[1]), "+f"(c[2]), "+f"(c[3])
        : "r"(a[0]), "r"(a[1]), "r"(a[2]), "r"(a[3]), "r"(b[0]), "r"(b[1]));
}
// fp16 m16n8k16 (attention S and PV)
__device__ __forceinline__ void mma16h(float* c, const uint32_t* a, const uint32_t* b) {
    asm volatile(
        "mma.sync.aligned.m16n8k16.row.col.f32.f16.f16.f32 "
        "{%0,%1,%2,%3}, {%4,%5,%6,%7}, {%8,%9}, {%0,%1,%2,%3};"
        : "+f"(c[0]), "+f"(c[1]), "+f"(c[2]), "+f"(c[3])
        : "r"(a[0]), "r"(a[1]), "r"(a[2]), "r"(a[3]), "r"(b[0]), "r"(b[1]));
}
__device__ __forceinline__ void ldsm4(uint32_t* r, uint32_t a) {
    asm volatile("ldmatrix.sync.aligned.m8n8.x4.b16 {%0,%1,%2,%3}, [%4];"
        : "=r"(r[0]), "=r"(r[1]), "=r"(r[2]), "=r"(r[3]) : "r"(a));
}
__device__ __forceinline__ void ldsm4t(uint32_t* r, uint32_t a) {
    asm volatile("ldmatrix.sync.aligned.m8n8.x4.trans.b16 {%0,%1,%2,%3}, [%4];"
        : "=r"(r[0]), "=r"(r[1]), "=r"(r[2]), "=r"(r[3]) : "r"(a));
}
__device__ __forceinline__ float fexp2(float x) {
    x = fmaxf(x, -100.0f);
    float t = x + 12582912.0f;
    float f = x - (t - 12582912.0f);
    int   sc = __float_as_int(t) << 23;
    float p = 0.0013333558f;
    p = fmaf(p, f, 0.0096181291f);
    p = fmaf(p, f, 0.0555041087f);
    p = fmaf(p, f, 0.2402265069f);
    p = fmaf(p, f, 0.6931471806f);
    p = fmaf(p, f, 1.0f);
    return __int_as_float(__float_as_int(p) + sc);
}

// ---------------------------------------------------------------------------
// Kernel 0 (merged): blocks [0,144): Wc = Wa@Wt (fp32) -> bf16 h/l
//                    blocks [144, 144+3072): split X -> bf16 h/l
// ---------------------------------------------------------------------------
#define WC_BLKS  (NH * 12)
#define CVT_BLKS (NB * NSEQ * HIDD / 2048)

__global__ __launch_bounds__(256) void k_pre(const float* __restrict__ X,
                                             const float* __restrict__ Wt,
                                             const float* __restrict__ Wa) {
    if (blockIdx.x >= WC_BLKS) {
        size_t t = (size_t)(blockIdx.x - WC_BLKS) * 256 + threadIdx.x;
        float4 v0 = *(const float4*)&X[t * 8];
        float4 v1 = *(const float4*)&X[t * 8 + 4];
        uint4 hp, lp;
        split2(v0.x, v0.y, hp.x, lp.x);
        split2(v0.z, v0.w, hp.y, lp.y);
        split2(v1.x, v1.y, hp.z, lp.z);
        split2(v1.z, v1.w, hp.w, lp.w);
        *(uint4*)&g_Xh[t * 4] = hp;
        *(uint4*)&g_Xl[t * 4] = lp;
        return;
    }
    const int h  = blockIdx.x / 12;
    const int d0 = (blockIdx.x % 12) * 64;
    __shared__ float Wa_s[64 * 36];
    __shared__ float Wt_s[32 * 68];

    const int tid = threadIdx.x;
    const int te = tid / 16;
    const int td = tid % 16;

    float acc[4][4];
#pragma unroll
    for (int i = 0; i < 4; i++)
#pragma unroll
        for (int j = 0; j < 4; j++) acc[i][j] = 0.f;

    for (int l0 = 0; l0 < LR; l0 += 32) {
#pragma unroll
        for (int it = 0; it < 2; it++) {
            int f = tid + it * 256;
            int e = f / 8, l4 = f % 8;
            float4 v = *(const float4*)&Wa[((size_t)h * 64 + e) * LR + l0 + l4 * 4];
            *(float4*)&Wa_s[e * 36 + l4 * 4] = v;
        }
#pragma unroll
        for (int it = 0; it < 2; it++) {
            int f = tid + it * 256;
            int l = f / 16, c4 = f % 16;
            float4 v = *(const float4*)&Wt[((size_t)h * LR + l0 + l) * HIDD + d0 + c4 * 4];
            *(float4*)&Wt_s[l * 68 + c4 * 4] = v;
        }
        __syncthreads();
#pragma unroll
        for (int l = 0; l < 32; l++) {
            float a[4];
#pragma unroll
            for (int i = 0; i < 4; i++) a[i] = Wa_s[(te * 4 + i) * 36 + l];
            float w[4];
            *(float4*)w = *(const float4*)&Wt_s[l * 68 + td * 4];
#pragma unroll
            for (int i = 0; i < 4; i++)
#pragma unroll
                for (int j = 0; j < 4; j++) acc[i][j] = fmaf(a[i], w[j], acc[i][j]);
        }
        __syncthreads();
    }
#pragma unroll
    for (int i = 0; i < 4; i++) {
        uint32_t h0, l0u, h1, l1u;
        split2(acc[i][0], acc[i][1], h0, l0u);
        split2(acc[i][2], acc[i][3], h1, l1u);
        size_t base = ((size_t)h * HD + te * 4 + i) * (HIDD / 2) + d0 / 2 + td * 2;
        *(uint2*)&g_Wh[base] = make_uint2(h0, h1);
        *(uint2*)&g_Wl[base] = make_uint2(l0u, l1u);
    }
}

// ---------------------------------------------------------------------------
// Kernel 1: t = X * Wc^T via bf16 split 3-term mma; writes fp16 t only
// ---------------------------------------------------------------------------
#define PS_XH 0
#define PS_XL 2560
#define PS_WH 5120
#define PS_WL 6400
#define PS_SZ 7680
#define PROJ_SMEM_BYTES (2 * PS_SZ * 4)
#define NKIT  (HIDD / 32)

__global__ __launch_bounds__(256, 2) void k_proj_mma(int dummy) {
    extern __shared__ uint32_t su[];
    const uint32_t smb = smem_u32(su);

    const int bh = blockIdx.y, b = bh / NH, h = bh % NH;
    const int n0 = blockIdx.x * 128;
    const int tid = threadIdx.x, wid = tid >> 5, lid = tid & 31;
    const int mw = wid & 3, nw = wid >> 2;
    const int g = lid >> 2, t4 = lid & 3;
    const int mrow = mw * 32, ncol = nw * 32;

    const uint32_t* Xh = g_Xh + (size_t)(b * NSEQ + n0) * (HIDD / 2);
    const uint32_t* Xl = g_Xl + (size_t)(b * NSEQ + n0) * (HIDD / 2);
    const uint32_t* Wh = g_Wh + (size_t)h * HD * (HIDD / 2);
    const uint32_t* Wl = g_Wl + (size_t)h * HD * (HIDD / 2);

    auto issue = [&](int ki) {
        const int st = (ki & 1) * PS_SZ;
        const int k2 = ki * 16;
#pragma unroll
        for (int it = 0; it < 2; it++) {
            int f = tid + it * 256;
            int r = f >> 2, c4 = (f & 3) * 4;
            uint32_t d0 = smb + (uint32_t)(st + PS_XH + r * 20 + c4) * 4u;
            uint32_t d1 = smb + (uint32_t)(st + PS_XL + r * 20 + c4) * 4u;
            asm volatile("cp.async.cg.shared.global [%0], [%1], 16;"
                         :: "r"(d0), "l"(Xh + (size_t)r * (HIDD / 2) + k2 + c4));
            asm volatile("cp.async.cg.shared.global [%0], [%1], 16;"
                         :: "r"(d1), "l"(Xl + (size_t)r * (HIDD / 2) + k2 + c4));
        }
        {
            int r = tid >> 2, c4 = (tid & 3) * 4;
            uint32_t d0 = smb + (uint32_t)(st + PS_WH + r * 20 + c4) * 4u;
            uint32_t d1 = smb + (uint32_t)(st + PS_WL + r * 20 + c4) * 4u;
            asm volatile("cp.async.cg.shared.global [%0], [%1], 16;"
                         :: "r"(d0), "l"(Wh + (size_t)r * (HIDD / 2) + k2 + c4));
            asm volatile("cp.async.cg.shared.global [%0], [%1], 16;"
                         :: "r"(d1), "l"(Wl + (size_t)r * (HIDD / 2) + k2 + c4));
        }
        asm volatile("cp.async.commit_group;" ::: "memory");
    };

    float acc[2][4][4];
#pragma unroll
    for (int mi = 0; mi < 2; mi++)
#pragma unroll
        for (int nj = 0; nj < 4; nj++)
#pragma unroll
            for (int r = 0; r < 4; r++) acc[mi][nj][r] = 0.f;

    issue(0);
    for (int ki = 0; ki < NKIT; ki++) {
        if (ki + 1 < NKIT) {
            issue(ki + 1);
            asm volatile("cp.async.wait_group 1;" ::: "memory");
        } else {
            asm volatile("cp.async.wait_group 0;" ::: "memory");
        }
        __syncthreads();

        const uint32_t* S = su + (ki & 1) * PS_SZ;
#pragma unroll
        for (int kk = 0; kk < 2; kk++) {
            const int ko = kk * 8;
            uint32_t ah[2][4], al[2][4];
#pragma unroll
            for (int mi = 0; mi < 2; mi++) {
                int base = (mrow + mi * 16 + g) * 20 + ko + t4;
                ah[mi][0] = S[PS_XH + base];
                ah[mi][1] = S[PS_XH + base + 160];
                ah[mi][2] = S[PS_XH + base + 4];
                ah[mi][3] = S[PS_XH + base + 164];
                al[mi][0] = S[PS_XL + base];
                al[mi][1] = S[PS_XL + base + 160];
                al[mi][2] = S[PS_XL + base + 4];
                al[mi][3] = S[PS_XL + base + 164];
            }
#pragma unroll
            for (int nj = 0; nj < 4; nj++) {
                int bb = (ncol + nj * 8 + g) * 20 + ko + t4;
                uint32_t bhv[2] = { S[PS_WH + bb], S[PS_WH + bb + 4] };
                uint32_t blv[2] = { S[PS_WL + bb], S[PS_WL + bb + 4] };
#pragma unroll
                for (int mi = 0; mi < 2; mi++) {
                    mma16(acc[mi][nj], ah[mi], bhv);
                    mma16(acc[mi][nj], ah[mi], blv);
                    mma16(acc[mi][nj], al[mi], bhv);
                }
            }
        }
        __syncthreads();
    }

    // epilogue: fp16 t only
    uint32_t* T16 = g_t16 + ((size_t)bh * NSEQ + n0) * (HD / 2);
#pragma unroll
    for (int mi = 0; mi < 2; mi++) {
        int r0 = mrow + mi * 16 + g;
#pragma unroll
        for (int nj = 0; nj < 4; nj++) {
            int cu = (ncol + nj * 8) / 2 + t4;
            T16[(size_t)r0 * (HD / 2) + cu] =
                packf16(acc[mi][nj][0], acc[mi][nj][1]);
            T16[(size_t)(r0 + 8) * (HD / 2) + cu] =
                packf16(acc[mi][nj][2], acc[mi][nj][3]);
        }
    }
}

// ---------------------------------------------------------------------------
// Kernel 2: all-fp16 flash attention. One fp16 tile serves as K AND V.
// Warp w owns q rows [w*16, w*16+16) over ALL keys. 1 sync/iter.
// S: fp16 m16n8k16 single term. PV: fp16, P via C->B frag identity.
// ---------------------------------------------------------------------------
#define A_Q    0                    // 128 * 144 fp16
#define A_KV   18432                // 2 stages * 64*144
#define A_KVST 9216
#define A_OB   36864                // float[2][64]
#define A_OL   37376                // float[128]
#define A_SM   37888

#define CE 0.052058774f             // 768^-0.5 * log2(e)

__global__ __launch_bounds__(256, 2) void k_attn7(const int* __restrict__ amask,
                                                  float* __restrict__ out) {
    extern __shared__ __align__(128) char smem[];
    const uint32_t smb = smem_u32(smem);

    const int bh = blockIdx.y, b = bh / NH, h = bh % NH;
    const int q0 = blockIdx.x * QT;
    const int tid = threadIdx.x, wid = tid >> 5, lid = tid & 31;
    const int g = lid >> 2, t4 = lid & 3;
    const int w16 = wid * 16;
    const int l7 = lid & 7;
    const int r8  = (lid & 8)  ? 8 : 0;
    const int r16 = (lid & 16) ? 8 : 0;

    const uint32_t* T16 = g_t16 + (size_t)bh * NSEQ * (HD / 2);
    const int* mb = amask + (size_t)b * NSEQ;
    float* biasf = (float*)(smem + A_OB);

    // prologue: Q fp16, KV tile 0, bias 0
#pragma unroll
    for (int it = 0; it < 4; it++) {
        int f = tid + it * 256;
        int r = f >> 3, c = f & 7;
        uint32_t dst = smb + A_Q + (uint32_t)(r * 144 + c * 16);
        asm volatile("cp.async.cg.shared.global [%0], [%1], 16;"
                     :: "r"(dst), "l"(T16 + (size_t)(q0 + r) * 32 + c * 4));
    }
#pragma unroll
    for (int it = 0; it < 2; it++) {
        int f = tid + it * 256;
        int r = f >> 3, c = f & 7;
        uint32_t dst = smb + A_KV + (uint32_t)(r * 144 + c * 16);
        asm volatile("cp.async.cg.shared.global [%0], [%1], 16;"
                     :: "r"(dst), "l"(T16 + (size_t)r * 32 + c * 4));
    }
    asm volatile("cp.async.commit_group;" ::: "memory");
    if (tid < 64) biasf[tid] = (mb[tid] == 0) ? -3000.f : 0.f;

    float rs0 = 0.f, rs1 = 0.f;
    float oacc[4][2][4];
#pragma unroll
    for (int me = 0; me < 4; me++)
#pragma unroll
        for (int n = 0; n < 2; n++)
#pragma unroll
            for (int r = 0; r < 4; r++) oacc[me][n][r] = 0.f;

    // ldmatrix lane offsets (R7-proven mapping, 144B row stride)
    const uint32_t qro = (uint32_t)((w16 + l7 + r8) * 144 + r16 * 2);
    const uint32_t kro = (uint32_t)((l7 + r16) * 144 + r8 * 2);

#pragma unroll 1
    for (int i = 0; i < NIT; i++) {
        asm volatile("cp.async.wait_group 0;" ::: "memory");
        __syncthreads();

        // prefetch next KV tile + bias
        if (i + 1 < NIT) {
            int j0 = (i + 1) * KT;
            uint32_t kst = A_KV + ((i + 1) & 1) * A_KVST;
#pragma unroll
            for (int it = 0; it < 2; it++) {
                int f = tid + it * 256;
                int r = f >> 3, c = f & 7;
                uint32_t dst = smb + kst + (uint32_t)(r * 144 + c * 16);
                asm volatile("cp.async.cg.shared.global [%0], [%1], 16;"
                             :: "r"(dst), "l"(T16 + (size_t)(j0 + r) * 32 + c * 4));
            }
            asm volatile("cp.async.commit_group;" ::: "memory");
            if (tid < 64)
                biasf[((i + 1) & 1) * 64 + tid] =
                    (mb[j0 + tid] == 0) ? -3000.f : 0.f;
        }

        const uint32_t kvb = smb + A_KV + (i & 1) * A_KVST;

        // ---- S = Q K^T (fp16, single term): 16q x 64key ----
        float sacc[8][4];
#pragma unroll
        for (int kg = 0; kg < 8; kg++)
#pragma unroll
            for (int r = 0; r < 4; r++) sacc[kg][r] = 0.f;

#pragma unroll
        for (int kb = 0; kb < 4; kb++) {
            uint32_t qf[4];
            ldsm4(qf, smb + A_Q + qro + kb * 32);
#pragma unroll
            for (int kt = 0; kt < 4; kt++) {
                uint32_t kf[4];
                ldsm4(kf, kvb + (uint32_t)(kt * 16 * 144) + kro + kb * 32);
                mma16h(sacc[kt * 2],     qf, kf);
                mma16h(sacc[kt * 2 + 1], qf, kf + 2);
            }
        }

        // ---- exp2 (masked bias) -> packed fp16 PV B-frags (registers) ----
        uint32_t u01[8], u23[8];
        const float* bi = biasf + (i & 1) * 64;
#pragma unroll
        for (int kg = 0; kg < 8; kg++) {
            float bx = bi[kg * 8 + 2 * t4];
            float by = bi[kg * 8 + 2 * t4 + 1];
            float* c = sacc[kg];
            float p0 = fexp2(fmaf(c[0], CE, bx));
            float p1 = fexp2(fmaf(c[1], CE, by));
            float p2 = fexp2(fmaf(c[2], CE, bx));
            float p3 = fexp2(fmaf(c[3], CE, by));
            rs0 += p0 + p1;
            rs1 += p2 + p3;
            u01[kg] = packf16(p0, p1);
            u23[kg] = packf16(p2, p3);
        }

        // ---- O^T += V^T P^T (V tile == KV tile, frags warp-local) ----
#pragma unroll
        for (int kt = 0; kt < 4; kt++) {
            uint32_t b0[2] = { u01[kt * 2], u01[kt * 2 + 1] };
            uint32_t b1[2] = { u23[kt * 2], u23[kt * 2 + 1] };
#pragma unroll
            for (int me = 0; me < 4; me++) {
                uint32_t ah[4];
                ldsm4t(ah, kvb + (uint32_t)((kt * 16 + l7 + r16) * 144
                                            + (me * 16 + r8) * 2));
                mma16h(oacc[me][0], ah, b0);
                mma16h(oacc[me][1], ah, b1);
            }
        }
    }

    // ---- epilogue ----
    rs0 += __shfl_xor_sync(0xffffffffu, rs0, 1);
    rs0 += __shfl_xor_sync(0xffffffffu, rs0, 2);
    rs1 += __shfl_xor_sync(0xffffffffu, rs1, 1);
    rs1 += __shfl_xor_sync(0xffffffffu, rs1, 2);
    float* lred = (float*)(smem + A_OL);
    if (t4 == 0) {
        lred[w16 + g] = rs0;
        lred[w16 + 8 + g] = rs1;
    }
    __syncthreads();

    const int qa = w16 + 2 * t4;
    const float inv0 = 1.f / lred[qa];
    const float inv1 = 1.f / lred[qa + 1];
    const float inv2 = 1.f / lred[qa + 8];
    const float inv3 = 1.f / lred[qa + 9];
    float* ob = out + ((size_t)b * NSEQ + q0 + qa) * (NH * HD) + h * HD;
#pragma unroll
    for (int me = 0; me < 4; me++) {
        int e0 = me * 16 + g;
        ob[e0]                   = oacc[me][0][0] * inv0;
        ob[NH * HD + e0]         = oacc[me][0][1] * inv1;
        ob[e0 + 8]               = oacc[me][0][2] * inv0;
        ob[NH * HD + e0 + 8]     = oacc[me][0][3] * inv1;
        ob[8 * NH * HD + e0]     = oacc[me][1][0] * inv2;
        ob[9 * NH * HD + e0]     = oacc[me][1][1] * inv3;
        ob[8 * NH * HD + e0 + 8] = oacc[me][1][2] * inv2;
        ob[9 * NH * HD + e0 + 8] = oacc[me][1][3] * inv3;
    }
}

// ---------------------------------------------------------------------------
extern "C" void kernel_launch(void* const* d_in, const int* in_sizes, int n_in,
                              void* d_out, int out_size) {
    const float* hidden = (const float*)d_in[0];
    const int*   amask  = (const int*)d_in[1];
    const float* Wt     = (const float*)d_in[2];
    const float* Wa     = (const float*)d_in[3];
    float* out = (float*)d_out;

    k_pre<<<WC_BLKS + CVT_BLKS, 256>>>(hidden, Wt, Wa);

    cudaFuncSetAttribute(k_proj_mma, cudaFuncAttributeMaxDynamicSharedMemorySize,
                         PROJ_SMEM_BYTES);
    k_proj_mma<<<dim3(NSEQ / 128, NB * NH), 256, PROJ_SMEM_BYTES>>>(0);

    cudaFuncSetAttribute(k_attn7, cudaFuncAttributeMaxDynamicSharedMemorySize,
                         A_SM);
    k_attn7<<<dim3(NSEQ / QT, NB * NH), 256, A_SM>>>(amask, out);
}

// round 11
// speedup vs baseline: 4.2613x; 1.0322x over previous
#include <cuda_runtime.h>
#include <cuda_bf16.h>
#include <cuda_fp16.h>
#include <cstdint>

#define NB    8
#define NSEQ  1024
#define HIDD  768
#define NH    12
#define LR    256
#define HD    64

#define QT    128
#define KT    64
#define NIT   (NSEQ / KT)

// scratch (no cudaMalloc allowed)
__device__ uint32_t g_Xh[NB * NSEQ * (HIDD / 2)];    // X bf16 hi, k-pair packed
__device__ uint32_t g_Xl[NB * NSEQ * (HIDD / 2)];
__device__ uint32_t g_Wh[NH * HD * (HIDD / 2)];      // Wc bf16 hi
__device__ uint32_t g_Wl[NH * HD * (HIDD / 2)];
__device__ uint32_t g_t16[NB * NH * NSEQ * (HD / 2)];// t fp16 e-pairs (q=k=v)

// ---------------------------------------------------------------------------
// helpers
// ---------------------------------------------------------------------------
__device__ __forceinline__ uint32_t smem_u32(const void* p) {
    uint32_t a;
    asm("{ .reg .u64 t; cvta.to.shared.u64 t, %1; cvt.u32.u64 %0, t; }"
        : "=r"(a) : "l"(p));
    return a;
}
__device__ __forceinline__ uint32_t packbf(float lo, float hi) {
    uint32_t r;
    asm("cvt.rn.bf16x2.f32 %0, %1, %2;" : "=r"(r) : "f"(hi), "f"(lo));
    return r;
}
__device__ __forceinline__ uint32_t packf16(float lo, float hi) {
    uint32_t r;
    asm("cvt.rn.f16x2.f32 %0, %1, %2;" : "=r"(r) : "f"(hi), "f"(lo));
    return r;
}
__device__ __forceinline__ void split2(float x0, float x1,
                                       uint32_t& hp, uint32_t& lp) {
    hp = packbf(x0, x1);
    float h0 = __uint_as_float(hp << 16);
    float h1 = __uint_as_float(hp & 0xffff0000u);
    lp = packbf(x0 - h0, x1 - h1);
}
// bf16 m16n8k16 (projection)
__device__ __forceinline__ void mma16(float* c, const uint32_t* a, const uint32_t* b) {
    asm volatile(
        "mma.sync.aligned.m16n8k16.row.col.f32.bf16.bf16.f32 "
        "{%0,%1,%2,%3}, {%4,%5,%6,%7}, {%8,%9}, {%0,%1,%2,%3};"
        : "+f"(c[0]), "+f"(c[1]), "+f"(c[2]), "+f"(c[3])
        : "r"(a[0]), "r"(a[1]), "r"(a[2]), "r"(a[3]), "r"(b[0]), "r"(b[1]));
}
// fp16 m16n8k16 (attention S and PV)
__device__ __forceinline__ void mma16h(float* c, const uint32_t* a, const uint32_t* b) {
    asm volatile(
        "mma.sync.aligned.m16n8k16.row.col.f32.f16.f16.f32 "
        "{%0,%1,%2,%3}, {%4,%5,%6,%7}, {%8,%9}, {%0,%1,%2,%3};"
        : "+f"(c[0]), "+f"(c[1]), "+f"(c[2]), "+f"(c[3])
        : "r"(a[0]), "r"(a[1]), "r"(a[2]), "r"(a[3]), "r"(b[0]), "r"(b[1]));
}
__device__ __forceinline__ void ldsm4(uint32_t* r, uint32_t a) {
    asm volatile("ldmatrix.sync.aligned.m8n8.x4.b16 {%0,%1,%2,%3}, [%4];"
        : "=r"(r[0]), "=r"(r[1]), "=r"(r[2]), "=r"(r[3]) : "r"(a));
}
__device__ __forceinline__ void ldsm4t(uint32_t* r, uint32_t a) {
    asm volatile("ldmatrix.sync.aligned.m8n8.x4.trans.b16 {%0,%1,%2,%3}, [%4];"
        : "=r"(r[0]), "=r"(r[1]), "=r"(r[2]), "=r"(r[3]) : "r"(a));
}
__device__ __forceinline__ float fexp2(float x) {
    x = fmaxf(x, -100.0f);
    float t = x + 12582912.0f;
    float f = x - (t - 12582912.0f);
    int   sc = __float_as_int(t) << 23;
    float p = 0.0013333558f;
    p = fmaf(p, f, 0.0096181291f);
    p = fmaf(p, f, 0.0555041087f);
    p = fmaf(p, f, 0.2402265069f);
    p = fmaf(p, f, 0.6931471806f);
    p = fmaf(p, f, 1.0f);
    return __int_as_float(__float_as_int(p) + sc);
}

// ---------------------------------------------------------------------------
// Kernel 0 (merged): blocks [0,144): Wc = Wa@Wt (fp32) -> bf16 h/l
//                    blocks [144, 144+3072): split X -> bf16 h/l
// ---------------------------------------------------------------------------
#define WC_BLKS  (NH * 12)
#define CVT_BLKS (NB * NSEQ * HIDD / 2048)

__global__ __launch_bounds__(256) void k_pre(const float* __restrict__ X,
                                             const float* __restrict__ Wt,
                                             const float* __restrict__ Wa) {
    if (blockIdx.x >= WC_BLKS) {
        size_t t = (size_t)(blockIdx.x - WC_BLKS) * 256 + threadIdx.x;
        float4 v0 = *(const float4*)&X[t * 8];
        float4 v1 = *(const float4*)&X[t * 8 + 4];
        uint4 hp, lp;
        split2(v0.x, v0.y, hp.x, lp.x);
        split2(v0.z, v0.w, hp.y, lp.y);
        split2(v1.x, v1.y, hp.z, lp.z);
        split2(v1.z, v1.w, hp.w, lp.w);
        *(uint4*)&g_Xh[t * 4] = hp;
        *(uint4*)&g_Xl[t * 4] = lp;
        return;
    }
    const int h  = blockIdx.x / 12;
    const int d0 = (blockIdx.x % 12) * 64;
    __shared__ float Wa_s[64 * 36];
    __shared__ float Wt_s[32 * 68];

    const int tid = threadIdx.x;
    const int te = tid / 16;
    const int td = tid % 16;

    float acc[4][4];
#pragma unroll
    for (int i = 0; i < 4; i++)
#pragma unroll
        for (int j = 0; j < 4; j++) acc[i][j] = 0.f;

    for (int l0 = 0; l0 < LR; l0 += 32) {
#pragma unroll
        for (int it = 0; it < 2; it++) {
            int f = tid + it * 256;
            int e = f / 8, l4 = f % 8;
            float4 v = *(const float4*)&Wa[((size_t)h * 64 + e) * LR + l0 + l4 * 4];
            *(float4*)&Wa_s[e * 36 + l4 * 4] = v;
        }
#pragma unroll
        for (int it = 0; it < 2; it++) {
            int f = tid + it * 256;
            int l = f / 16, c4 = f % 16;
            float4 v = *(const float4*)&Wt[((size_t)h * LR + l0 + l) * HIDD + d0 + c4 * 4];
            *(float4*)&Wt_s[l * 68 + c4 * 4] = v;
        }
        __syncthreads();
#pragma unroll
        for (int l = 0; l < 32; l++) {
            float a[4];
#pragma unroll
            for (int i = 0; i < 4; i++) a[i] = Wa_s[(te * 4 + i) * 36 + l];
            float w[4];
            *(float4*)w = *(const float4*)&Wt_s[l * 68 + td * 4];
#pragma unroll
            for (int i = 0; i < 4; i++)
#pragma unroll
                for (int j = 0; j < 4; j++) acc[i][j] = fmaf(a[i], w[j], acc[i][j]);
        }
        __syncthreads();
    }
#pragma unroll
    for (int i = 0; i < 4; i++) {
        uint32_t h0, l0u, h1, l1u;
        split2(acc[i][0], acc[i][1], h0, l0u);
        split2(acc[i][2], acc[i][3], h1, l1u);
        size_t base = ((size_t)h * HD + te * 4 + i) * (HIDD / 2) + d0 / 2 + td * 2;
        *(uint2*)&g_Wh[base] = make_uint2(h0, h1);
        *(uint2*)&g_Wl[base] = make_uint2(l0u, l1u);
    }
}

// ---------------------------------------------------------------------------
// Kernel 1: t = X * Wc^T, 3-term bf16 split (R9 numerics) with ldmatrix
// fragment fetch. smem rows 80B stride (conflict-free), K-tile 32, 2 stages.
// CTA: 128 n x 64 e of one (b,h); 8 warps (4m x 2n).
// ---------------------------------------------------------------------------
#define PJ_X    0                      // per stage: Xh 128*80, Xl at +10240
#define PJ_XST  20480
#define PJ_W    40960                  // per stage: Wh 64*80, Wl at +5120
#define PJ_WST  10240
#define PROJ_SMEM_BYTES 61440
#define NKIT  (HIDD / 32)              // 24

__global__ __launch_bounds__(256, 2) void k_proj_mma(int dummy) {
    extern __shared__ __align__(128) char smem[];
    const uint32_t smb = smem_u32(smem);

    const int bh = blockIdx.y, b = bh / NH, h = bh % NH;
    const int n0 = blockIdx.x * 128;
    const int tid = threadIdx.x, wid = tid >> 5, lid = tid & 31;
    const int mw = wid & 3, nw = wid >> 2;
    const int g = lid >> 2, t4 = lid & 3;
    const int mrow = mw * 32, ncol = nw * 32;
    const int l7 = lid & 7;
    const int r8  = (lid & 8)  ? 8 : 0;
    const int r16 = (lid & 16) ? 8 : 0;

    const uint32_t* Xh = g_Xh + (size_t)(b * NSEQ + n0) * (HIDD / 2);
    const uint32_t* Xl = g_Xl + (size_t)(b * NSEQ + n0) * (HIDD / 2);
    const uint32_t* Wh = g_Wh + (size_t)h * HD * (HIDD / 2);
    const uint32_t* Wl = g_Wl + (size_t)h * HD * (HIDD / 2);

    auto issue = [&](int ki) {
        const uint32_t xb = smb + PJ_X + (ki & 1) * PJ_XST;
        const uint32_t wb = smb + PJ_W + (ki & 1) * PJ_WST;
        const int k4 = ki * 16;   // u32 offset of k-tile in 384-u32 row
        // X: 128 rows x 64B (h and l)
#pragma unroll
        for (int it = 0; it < 2; it++) {
            int f = tid + it * 256;
            int r = f >> 2, c = f & 3;
            uint32_t d = (uint32_t)(r * 80 + c * 16);
            asm volatile("cp.async.cg.shared.global [%0], [%1], 16;"
                         :: "r"(xb + d), "l"(Xh + (size_t)r * 384 + k4 + c * 4));
            asm volatile("cp.async.cg.shared.global [%0], [%1], 16;"
                         :: "r"(xb + 10240 + d), "l"(Xl + (size_t)r * 384 + k4 + c * 4));
        }
        // W: 64 rows x 64B (h and l)
        {
            int r = tid >> 2, c = tid & 3;
            uint32_t d = (uint32_t)(r * 80 + c * 16);
            asm volatile("cp.async.cg.shared.global [%0], [%1], 16;"
                         :: "r"(wb + d), "l"(Wh + (size_t)r * 384 + k4 + c * 4));
            asm volatile("cp.async.cg.shared.global [%0], [%1], 16;"
                         :: "r"(wb + 5120 + d), "l"(Wl + (size_t)r * 384 + k4 + c * 4));
        }
        asm volatile("cp.async.commit_group;" ::: "memory");
    };

    float acc[2][4][4];
#pragma unroll
    for (int mi = 0; mi < 2; mi++)
#pragma unroll
        for (int nj = 0; nj < 4; nj++)
#pragma unroll
            for (int r = 0; r < 4; r++) acc[mi][nj][r] = 0.f;

    // ldmatrix lane offsets (attn-proven mappings, stride 80)
    const uint32_t aro = (uint32_t)((mrow + l7 + r8) * 80 + r16 * 2);
    const uint32_t bro = (uint32_t)((ncol + l7 + r16) * 80 + r8 * 2);

    issue(0);
    for (int ki = 0; ki < NKIT; ki++) {
        if (ki + 1 < NKIT) {
            issue(ki + 1);
            asm volatile("cp.async.wait_group 1;" ::: "memory");
        } else {
            asm volatile("cp.async.wait_group 0;" ::: "memory");
        }
        __syncthreads();

        const uint32_t xb = smb + PJ_X + (ki & 1) * PJ_XST;
        const uint32_t wb = smb + PJ_W + (ki & 1) * PJ_WST;
#pragma unroll
        for (int c16 = 0; c16 < 2; c16++) {
            const uint32_t off = c16 * 32;
            uint32_t xh0[4], xh1[4], xl0[4], xl1[4];
            ldsm4(xh0, xb + aro + off);
            ldsm4(xh1, xb + aro + 16 * 80 + off);
            ldsm4(xl0, xb + 10240 + aro + off);
            ldsm4(xl1, xb + 10240 + aro + 16 * 80 + off);
            uint32_t wh0[4], wh1[4], wl0[4], wl1[4];
            ldsm4(wh0, wb + bro + off);
            ldsm4(wh1, wb + bro + 16 * 80 + off);
            ldsm4(wl0, wb + 5120 + bro + off);
            ldsm4(wl1, wb + 5120 + bro + 16 * 80 + off);
            // 3-term: Xh*Wh + Xh*Wl + Xl*Wh
            mma16(acc[0][0], xh0, wh0);     mma16(acc[0][0], xh0, wl0);
            mma16(acc[0][0], xl0, wh0);
            mma16(acc[0][1], xh0, wh0 + 2); mma16(acc[0][1], xh0, wl0 + 2);
            mma16(acc[0][1], xl0, wh0 + 2);
            mma16(acc[0][2], xh0, wh1);     mma16(acc[0][2], xh0, wl1);
            mma16(acc[0][2], xl0, wh1);
            mma16(acc[0][3], xh0, wh1 + 2); mma16(acc[0][3], xh0, wl1 + 2);
            mma16(acc[0][3], xl0, wh1 + 2);
            mma16(acc[1][0], xh1, wh0);     mma16(acc[1][0], xh1, wl0);
            mma16(acc[1][0], xl1, wh0);
            mma16(acc[1][1], xh1, wh0 + 2); mma16(acc[1][1], xh1, wl0 + 2);
            mma16(acc[1][1], xl1, wh0 + 2);
            mma16(acc[1][2], xh1, wh1);     mma16(acc[1][2], xh1, wl1);
            mma16(acc[1][2], xl1, wh1);
            mma16(acc[1][3], xh1, wh1 + 2); mma16(acc[1][3], xh1, wl1 + 2);
            mma16(acc[1][3], xl1, wh1 + 2);
        }
        __syncthreads();
    }

    // epilogue: fp16 t
    uint32_t* T16 = g_t16 + ((size_t)bh * NSEQ + n0) * (HD / 2);
#pragma unroll
    for (int mi = 0; mi < 2; mi++) {
        int r0 = mrow + mi * 16 + g;
#pragma unroll
        for (int nj = 0; nj < 4; nj++) {
            int cu = (ncol + nj * 8) / 2 + t4;
            T16[(size_t)r0 * (HD / 2) + cu] =
                packf16(acc[mi][nj][0], acc[mi][nj][1]);
            T16[(size_t)(r0 + 8) * (HD / 2) + cu] =
                packf16(acc[mi][nj][2], acc[mi][nj][3]);
        }
    }
}

// ---------------------------------------------------------------------------
// Kernel 2: all-fp16 flash attention (unchanged from round 9).
// ---------------------------------------------------------------------------
#define A_Q    0                    // 128 * 144 fp16
#define A_KV   18432                // 2 stages * 64*144
#define A_KVST 9216
#define A_OB   36864                // float[2][64]
#define A_OL   37376                // float[128]
#define A_SM   37888

#define CE 0.052058774f             // 768^-0.5 * log2(e)

__global__ __launch_bounds__(256, 2) void k_attn7(const int* __restrict__ amask,
                                                  float* __restrict__ out) {
    extern __shared__ __align__(128) char smem[];
    const uint32_t smb = smem_u32(smem);

    const int bh = blockIdx.y, b = bh / NH, h = bh % NH;
    const int q0 = blockIdx.x * QT;
    const int tid = threadIdx.x, wid = tid >> 5, lid = tid & 31;
    const int g = lid >> 2, t4 = lid & 3;
    const int w16 = wid * 16;
    const int l7 = lid & 7;
    const int r8  = (lid & 8)  ? 8 : 0;
    const int r16 = (lid & 16) ? 8 : 0;

    const uint32_t* T16 = g_t16 + (size_t)bh * NSEQ * (HD / 2);
    const int* mb = amask + (size_t)b * NSEQ;
    float* biasf = (float*)(smem + A_OB);

    // prologue: Q fp16, KV tile 0, bias 0
#pragma unroll
    for (int it = 0; it < 4; it++) {
        int f = tid + it * 256;
        int r = f >> 3, c = f & 7;
        uint32_t dst = smb + A_Q + (uint32_t)(r * 144 + c * 16);
        asm volatile("cp.async.cg.shared.global [%0], [%1], 16;"
                     :: "r"(dst), "l"(T16 + (size_t)(q0 + r) * 32 + c * 4));
    }
#pragma unroll
    for (int it = 0; it < 2; it++) {
        int f = tid + it * 256;
        int r = f >> 3, c = f & 7;
        uint32_t dst = smb + A_KV + (uint32_t)(r * 144 + c * 16);
        asm volatile("cp.async.cg.shared.global [%0], [%1], 16;"
                     :: "r"(dst), "l"(T16 + (size_t)r * 32 + c * 4));
    }
    asm volatile("cp.async.commit_group;" ::: "memory");
    if (tid < 64) biasf[tid] = (mb[tid] == 0) ? -3000.f : 0.f;

    float rs0 = 0.f, rs1 = 0.f;
    float oacc[4][2][4];
#pragma unroll
    for (int me = 0; me < 4; me++)
#pragma unroll
        for (int n = 0; n < 2; n++)
#pragma unroll
            for (int r = 0; r < 4; r++) oacc[me][n][r] = 0.f;

    const uint32_t qro = (uint32_t)((w16 + l7 + r8) * 144 + r16 * 2);
    const uint32_t kro = (uint32_t)((l7 + r16) * 144 + r8 * 2);

#pragma unroll 1
    for (int i = 0; i < NIT; i++) {
        asm volatile("cp.async.wait_group 0;" ::: "memory");
        __syncthreads();

        if (i + 1 < NIT) {
            int j0 = (i + 1) * KT;
            uint32_t kst = A_KV + ((i + 1) & 1) * A_KVST;
#pragma unroll
            for (int it = 0; it < 2; it++) {
                int f = tid + it * 256;
                int r = f >> 3, c = f & 7;
                uint32_t dst = smb + kst + (uint32_t)(r * 144 + c * 16);
                asm volatile("cp.async.cg.shared.global [%0], [%1], 16;"
                             :: "r"(dst), "l"(T16 + (size_t)(j0 + r) * 32 + c * 4));
            }
            asm volatile("cp.async.commit_group;" ::: "memory");
            if (tid < 64)
                biasf[((i + 1) & 1) * 64 + tid] =
                    (mb[j0 + tid] == 0) ? -3000.f : 0.f;
        }

        const uint32_t kvb = smb + A_KV + (i & 1) * A_KVST;

        // ---- S = Q K^T (fp16): 16q x 64key ----
        float sacc[8][4];
#pragma unroll
        for (int kg = 0; kg < 8; kg++)
#pragma unroll
            for (int r = 0; r < 4; r++) sacc[kg][r] = 0.f;

#pragma unroll
        for (int kb = 0; kb < 4; kb++) {
            uint32_t qf[4];
            ldsm4(qf, smb + A_Q + qro + kb * 32);
#pragma unroll
            for (int kt = 0; kt < 4; kt++) {
                uint32_t kf[4];
                ldsm4(kf, kvb + (uint32_t)(kt * 16 * 144) + kro + kb * 32);
                mma16h(sacc[kt * 2],     qf, kf);
                mma16h(sacc[kt * 2 + 1], qf, kf + 2);
            }
        }

        // ---- exp2 (masked bias) -> packed fp16 PV B-frags ----
        uint32_t u01[8], u23[8];
        const float* bi = biasf + (i & 1) * 64;
#pragma unroll
        for (int kg = 0; kg < 8; kg++) {
            float bx = bi[kg * 8 + 2 * t4];
            float by = bi[kg * 8 + 2 * t4 + 1];
            float* c = sacc[kg];
            float p0 = fexp2(fmaf(c[0], CE, bx));
            float p1 = fexp2(fmaf(c[1], CE, by));
            float p2 = fexp2(fmaf(c[2], CE, bx));
            float p3 = fexp2(fmaf(c[3], CE, by));
            rs0 += p0 + p1;
            rs1 += p2 + p3;
            u01[kg] = packf16(p0, p1);
            u23[kg] = packf16(p2, p3);
        }

        // ---- O^T += V^T P^T (V tile == KV tile) ----
#pragma unroll
        for (int kt = 0; kt < 4; kt++) {
            uint32_t b0[2] = { u01[kt * 2], u01[kt * 2 + 1] };
            uint32_t b1[2] = { u23[kt * 2], u23[kt * 2 + 1] };
#pragma unroll
            for (int me = 0; me < 4; me++) {
                uint32_t ah[4];
                ldsm4t(ah, kvb + (uint32_t)((kt * 16 + l7 + r16) * 144
                                            + (me * 16 + r8) * 2));
                mma16h(oacc[me][0], ah, b0);
                mma16h(oacc[me][1], ah, b1);
            }
        }
    }

    // ---- epilogue ----
    rs0 += __shfl_xor_sync(0xffffffffu, rs0, 1);
    rs0 += __shfl_xor_sync(0xffffffffu, rs0, 2);
    rs1 += __shfl_xor_sync(0xffffffffu, rs1, 1);
    rs1 += __shfl_xor_sync(0xffffffffu, rs1, 2);
    float* lred = (float*)(smem + A_OL);
    if (t4 == 0) {
        lred[w16 + g] = rs0;
        lred[w16 + 8 + g] = rs1;
    }
    __syncthreads();

    const int qa = w16 + 2 * t4;
    const float inv0 = 1.f / lred[qa];
    const float inv1 = 1.f / lred[qa + 1];
    const float inv2 = 1.f / lred[qa + 8];
    const float inv3 = 1.f / lred[qa + 9];
    float* ob = out + ((size_t)b * NSEQ + q0 + qa) * (NH * HD) + h * HD;
#pragma unroll
    for (int me = 0; me < 4; me++) {
        int e0 = me * 16 + g;
        ob[e0]                   = oacc[me][0][0] * inv0;
        ob[NH * HD + e0]         = oacc[me][0][1] * inv1;
        ob[e0 + 8]               = oacc[me][0][2] * inv0;
        ob[NH * HD + e0 + 8]     = oacc[me][0][3] * inv1;
        ob[8 * NH * HD + e0]     = oacc[me][1][0] * inv2;
        ob[9 * NH * HD + e0]     = oacc[me][1][1] * inv3;
        ob[8 * NH * HD + e0 + 8] = oacc[me][1][2] * inv2;
        ob[9 * NH * HD + e0 + 8] = oacc[me][1][3] * inv3;
    }
}

// ---------------------------------------------------------------------------
extern "C" void kernel_launch(void* const* d_in, const int* in_sizes, int n_in,
                              void* d_out, int out_size) {
    const float* hidden = (const float*)d_in[0];
    const int*   amask  = (const int*)d_in[1];
    const float* Wt     = (const float*)d_in[2];
    const float* Wa     = (const float*)d_in[3];
    float* out = (float*)d_out;

    k_pre<<<WC_BLKS + CVT_BLKS, 256>>>(hidden, Wt, Wa);

    cudaFuncSetAttribute(k_proj_mma, cudaFuncAttributeMaxDynamicSharedMemorySize,
                         PROJ_SMEM_BYTES);
    k_proj_mma<<<dim3(NSEQ / 128, NB * NH), 256, PROJ_SMEM_BYTES>>>(0);

    cudaFuncSetAttribute(k_attn7, cudaFuncAttributeMaxDynamicSharedMemorySize,
                         A_SM);
    k_attn7<<<dim3(NSEQ / QT, NB * NH), 256, A_SM>>>(amask, out);
}

// round 12
// speedup vs baseline: 4.6656x; 1.0949x over previous
#include <cuda_runtime.h>
#include <cuda_bf16.h>
#include <cuda_fp16.h>
#include <cstdint>

#define NB    8
#define NSEQ  1024
#define HIDD  768
#define NH    12
#define LR    256
#define HD    64

#define QT    128
#define KT    64
#define NIT   (NSEQ / KT)

// scratch (no cudaMalloc allowed)
__device__ uint32_t g_Xh[NB * NSEQ * (HIDD / 2)];    // X bf16 hi, k-pair packed
__device__ uint32_t g_Xl[NB * NSEQ * (HIDD / 2)];
__device__ uint32_t g_Wh[NH * HD * (HIDD / 2)];      // Wc bf16 hi
__device__ uint32_t g_Wl[NH * HD * (HIDD / 2)];
__device__ uint32_t g_t16[NB * NH * NSEQ * (HD / 2)];// t fp16 e-pairs (q=k=v)

// ---------------------------------------------------------------------------
// helpers
// ---------------------------------------------------------------------------
__device__ __forceinline__ uint32_t smem_u32(const void* p) {
    uint32_t a;
    asm("{ .reg .u64 t; cvta.to.shared.u64 t, %1; cvt.u32.u64 %0, t; }"
        : "=r"(a) : "l"(p));
    return a;
}
__device__ __forceinline__ uint32_t packbf(float lo, float hi) {
    uint32_t r;
    asm("cvt.rn.bf16x2.f32 %0, %1, %2;" : "=r"(r) : "f"(hi), "f"(lo));
    return r;
}
__device__ __forceinline__ uint32_t packf16(float lo, float hi) {
    uint32_t r;
    asm("cvt.rn.f16x2.f32 %0, %1, %2;" : "=r"(r) : "f"(hi), "f"(lo));
    return r;
}
__device__ __forceinline__ void split2(float x0, float x1,
                                       uint32_t& hp, uint32_t& lp) {
    hp = packbf(x0, x1);
    float h0 = __uint_as_float(hp << 16);
    float h1 = __uint_as_float(hp & 0xffff0000u);
    lp = packbf(x0 - h0, x1 - h1);
}
__device__ __forceinline__ float ex2(float x) {
    float r; asm("ex2.approx.f32 %0, %1;" : "=f"(r) : "f"(x)); return r;
}
// bf16 m16n8k16 (projection)
__device__ __forceinline__ void mma16(float* c, const uint32_t* a, const uint32_t* b) {
    asm volatile(
        "mma.sync.aligned.m16n8k16.row.col.f32.bf16.bf16.f32 "
        "{%0,%1,%2,%3}, {%4,%5,%6,%7}, {%8,%9}, {%0,%1,%2,%3};"
        : "+f"(c[0]), "+f"(c[1]), "+f"(c[2]), "+f"(c[3])
        : "r"(a[0]), "r"(a[1]), "r"(a[2]), "r"(a[3]), "r"(b[0]), "r"(b[1]));
}
// fp16 m16n8k16 (attention S and PV)
__device__ __forceinline__ void mma16h(float* c, const uint32_t* a, const uint32_t* b) {
    asm volatile(
        "mma.sync.aligned.m16n8k16.row.col.f32.f16.f16.f32 "
        "{%0,%1,%2,%3}, {%4,%5,%6,%7}, {%8,%9}, {%0,%1,%2,%3};"
        : "+f"(c[0]), "+f"(c[1]), "+f"(c[2]), "+f"(c[3])
        : "r"(a[0]), "r"(a[1]), "r"(a[2]), "r"(a[3]), "r"(b[0]), "r"(b[1]));
}
__device__ __forceinline__ void ldsm4(uint32_t* r, uint32_t a) {
    asm volatile("ldmatrix.sync.aligned.m8n8.x4.b16 {%0,%1,%2,%3}, [%4];"
        : "=r"(r[0]), "=r"(r[1]), "=r"(r[2]), "=r"(r[3]) : "r"(a));
}
__device__ __forceinline__ void ldsm4t(uint32_t* r, uint32_t a) {
    asm volatile("ldmatrix.sync.aligned.m8n8.x4.trans.b16 {%0,%1,%2,%3}, [%4];"
        : "=r"(r[0]), "=r"(r[1]), "=r"(r[2]), "=r"(r[3]) : "r"(a));
}

// ---------------------------------------------------------------------------
// Kernel 0 (merged): blocks [0,144): Wc = Wa@Wt (fp32) -> bf16 h/l
//                    blocks [144, 144+1536): split X -> bf16 h/l (16 f/thread)
// ---------------------------------------------------------------------------
#define WC_BLKS  (NH * 12)
#define CVT_BLKS (NB * NSEQ * HIDD / 4096)   // 1536

__global__ __launch_bounds__(256) void k_pre(const float* __restrict__ X,
                                             const float* __restrict__ Wt,
                                             const float* __restrict__ Wa) {
    if (blockIdx.x >= WC_BLKS) {
        size_t t = (size_t)(blockIdx.x - WC_BLKS) * 256 + threadIdx.x;
        float4 v[4];
#pragma unroll
        for (int i = 0; i < 4; i++) v[i] = *(const float4*)&X[t * 16 + i * 4];
        uint4 hp[2], lp[2];
#pragma unroll
        for (int i = 0; i < 2; i++) {
            split2(v[i * 2].x, v[i * 2].y, hp[i].x, lp[i].x);
            split2(v[i * 2].z, v[i * 2].w, hp[i].y, lp[i].y);
            split2(v[i * 2 + 1].x, v[i * 2 + 1].y, hp[i].z, lp[i].z);
            split2(v[i * 2 + 1].z, v[i * 2 + 1].w, hp[i].w, lp[i].w);
        }
        *(uint4*)&g_Xh[t * 8]     = hp[0];
        *(uint4*)&g_Xh[t * 8 + 4] = hp[1];
        *(uint4*)&g_Xl[t * 8]     = lp[0];
        *(uint4*)&g_Xl[t * 8 + 4] = lp[1];
        return;
    }
    const int h  = blockIdx.x / 12;
    const int d0 = (blockIdx.x % 12) * 64;
    __shared__ float Wa_s[64 * 36];
    __shared__ float Wt_s[32 * 68];

    const int tid = threadIdx.x;
    const int te = tid / 16;
    const int td = tid % 16;

    float acc[4][4];
#pragma unroll
    for (int i = 0; i < 4; i++)
#pragma unroll
        for (int j = 0; j < 4; j++) acc[i][j] = 0.f;

    for (int l0 = 0; l0 < LR; l0 += 32) {
#pragma unroll
        for (int it = 0; it < 2; it++) {
            int f = tid + it * 256;
            int e = f / 8, l4 = f % 8;
            float4 v = *(const float4*)&Wa[((size_t)h * 64 + e) * LR + l0 + l4 * 4];
            *(float4*)&Wa_s[e * 36 + l4 * 4] = v;
        }
#pragma unroll
        for (int it = 0; it < 2; it++) {
            int f = tid + it * 256;
            int l = f / 16, c4 = f % 16;
            float4 v = *(const float4*)&Wt[((size_t)h * LR + l0 + l) * HIDD + d0 + c4 * 4];
            *(float4*)&Wt_s[l * 68 + c4 * 4] = v;
        }
        __syncthreads();
#pragma unroll
        for (int l = 0; l < 32; l++) {
            float a[4];
#pragma unroll
            for (int i = 0; i < 4; i++) a[i] = Wa_s[(te * 4 + i) * 36 + l];
            float w[4];
            *(float4*)w = *(const float4*)&Wt_s[l * 68 + td * 4];
#pragma unroll
            for (int i = 0; i < 4; i++)
#pragma unroll
                for (int j = 0; j < 4; j++) acc[i][j] = fmaf(a[i], w[j], acc[i][j]);
        }
        __syncthreads();
    }
#pragma unroll
    for (int i = 0; i < 4; i++) {
        uint32_t h0, l0u, h1, l1u;
        split2(acc[i][0], acc[i][1], h0, l0u);
        split2(acc[i][2], acc[i][3], h1, l1u);
        size_t base = ((size_t)h * HD + te * 4 + i) * (HIDD / 2) + d0 / 2 + td * 2;
        *(uint2*)&g_Wh[base] = make_uint2(h0, h1);
        *(uint2*)&g_Wl[base] = make_uint2(l0u, l1u);
    }
}

// ---------------------------------------------------------------------------
// Kernel 1: t = X * Wc^T, 3-term bf16 split, ldmatrix frags, single-sync loop.
// ---------------------------------------------------------------------------
#define PJ_X    0                      // per stage: Xh 128*80, Xl at +10240
#define PJ_XST  20480
#define PJ_W    40960                  // per stage: Wh 64*80, Wl at +5120
#define PJ_WST  10240
#define PROJ_SMEM_BYTES 61440
#define NKIT  (HIDD / 32)              // 24

__global__ __launch_bounds__(256, 2) void k_proj_mma(int dummy) {
    extern __shared__ __align__(128) char smem[];
    const uint32_t smb = smem_u32(smem);

    const int bh = blockIdx.y, b = bh / NH, h = bh % NH;
    const int n0 = blockIdx.x * 128;
    const int tid = threadIdx.x, wid = tid >> 5, lid = tid & 31;
    const int mw = wid & 3, nw = wid >> 2;
    const int g = lid >> 2, t4 = lid & 3;
    const int mrow = mw * 32, ncol = nw * 32;
    const int l7 = lid & 7;
    const int r8  = (lid & 8)  ? 8 : 0;
    const int r16 = (lid & 16) ? 8 : 0;

    const uint32_t* Xh = g_Xh + (size_t)(b * NSEQ + n0) * (HIDD / 2);
    const uint32_t* Xl = g_Xl + (size_t)(b * NSEQ + n0) * (HIDD / 2);
    const uint32_t* Wh = g_Wh + (size_t)h * HD * (HIDD / 2);
    const uint32_t* Wl = g_Wl + (size_t)h * HD * (HIDD / 2);

    auto issue = [&](int ki) {
        const uint32_t xb = smb + PJ_X + (ki & 1) * PJ_XST;
        const uint32_t wb = smb + PJ_W + (ki & 1) * PJ_WST;
        const int k4 = ki * 16;
#pragma unroll
        for (int it = 0; it < 2; it++) {
            int f = tid + it * 256;
            int r = f >> 2, c = f & 3;
            uint32_t d = (uint32_t)(r * 80 + c * 16);
            asm volatile("cp.async.cg.shared.global [%0], [%1], 16;"
                         :: "r"(xb + d), "l"(Xh + (size_t)r * 384 + k4 + c * 4));
            asm volatile("cp.async.cg.shared.global [%0], [%1], 16;"
                         :: "r"(xb + 10240 + d), "l"(Xl + (size_t)r * 384 + k4 + c * 4));
        }
        {
            int r = tid >> 2, c = tid & 3;
            uint32_t d = (uint32_t)(r * 80 + c * 16);
            asm volatile("cp.async.cg.shared.global [%0], [%1], 16;"
                         :: "r"(wb + d), "l"(Wh + (size_t)r * 384 + k4 + c * 4));
            asm volatile("cp.async.cg.shared.global [%0], [%1], 16;"
                         :: "r"(wb + 5120 + d), "l"(Wl + (size_t)r * 384 + k4 + c * 4));
        }
        asm volatile("cp.async.commit_group;" ::: "memory");
    };

    float acc[2][4][4];
#pragma unroll
    for (int mi = 0; mi < 2; mi++)
#pragma unroll
        for (int nj = 0; nj < 4; nj++)
#pragma unroll
            for (int r = 0; r < 4; r++) acc[mi][nj][r] = 0.f;

    const uint32_t aro = (uint32_t)((mrow + l7 + r8) * 80 + r16 * 2);
    const uint32_t bro = (uint32_t)((ncol + l7 + r16) * 80 + r8 * 2);

    issue(0);
#pragma unroll 1
    for (int ki = 0; ki < NKIT; ki++) {
        asm volatile("cp.async.wait_group 0;" ::: "memory");
        __syncthreads();
        if (ki + 1 < NKIT) issue(ki + 1);

        const uint32_t xb = smb + PJ_X + (ki & 1) * PJ_XST;
        const uint32_t wb = smb + PJ_W + (ki & 1) * PJ_WST;
#pragma unroll
        for (int c16 = 0; c16 < 2; c16++) {
            const uint32_t off = c16 * 32;
            uint32_t xh0[4], xh1[4], xl0[4], xl1[4];
            ldsm4(xh0, xb + aro + off);
            ldsm4(xh1, xb + aro + 16 * 80 + off);
            ldsm4(xl0, xb + 10240 + aro + off);
            ldsm4(xl1, xb + 10240 + aro + 16 * 80 + off);
            uint32_t wh0[4], wh1[4], wl0[4], wl1[4];
            ldsm4(wh0, wb + bro + off);
            ldsm4(wh1, wb + bro + 16 * 80 + off);
            ldsm4(wl0, wb + 5120 + bro + off);
            ldsm4(wl1, wb + 5120 + bro + 16 * 80 + off);
            mma16(acc[0][0], xh0, wh0);     mma16(acc[0][0], xh0, wl0);
            mma16(acc[0][0], xl0, wh0);
            mma16(acc[0][1], xh0, wh0 + 2); mma16(acc[0][1], xh0, wl0 + 2);
            mma16(acc[0][1], xl0, wh0 + 2);
            mma16(acc[0][2], xh0, wh1);     mma16(acc[0][2], xh0, wl1);
            mma16(acc[0][2], xl0, wh1);
            mma16(acc[0][3], xh0, wh1 + 2); mma16(acc[0][3], xh0, wl1 + 2);
            mma16(acc[0][3], xl0, wh1 + 2);
            mma16(acc[1][0], xh1, wh0);     mma16(acc[1][0], xh1, wl0);
            mma16(acc[1][0], xl1, wh0);
            mma16(acc[1][1], xh1, wh0 + 2); mma16(acc[1][1], xh1, wl0 + 2);
            mma16(acc[1][1], xl1, wh0 + 2);
            mma16(acc[1][2], xh1, wh1);     mma16(acc[1][2], xh1, wl1);
            mma16(acc[1][2], xl1, wh1);
            mma16(acc[1][3], xh1, wh1 + 2); mma16(acc[1][3], xh1, wl1 + 2);
            mma16(acc[1][3], xl1, wh1 + 2);
        }
    }

    // epilogue: fp16 t
    uint32_t* T16 = g_t16 + ((size_t)bh * NSEQ + n0) * (HD / 2);
#pragma unroll
    for (int mi = 0; mi < 2; mi++) {
        int r0 = mrow + mi * 16 + g;
#pragma unroll
        for (int nj = 0; nj < 4; nj++) {
            int cu = (ncol + nj * 8) / 2 + t4;
            T16[(size_t)r0 * (HD / 2) + cu] =
                packf16(acc[mi][nj][0], acc[mi][nj][1]);
            T16[(size_t)(r0 + 8) * (HD / 2) + cu] =
                packf16(acc[mi][nj][2], acc[mi][nj][3]);
        }
    }
}

// ---------------------------------------------------------------------------
// Kernel 2: all-fp16 flash attention; exp via MUFU ex2.approx.
// ---------------------------------------------------------------------------
#define A_Q    0                    // 128 * 144 fp16
#define A_KV   18432                // 2 stages * 64*144
#define A_KVST 9216
#define A_OB   36864                // float[2][64]
#define A_OL   37376                // float[128]
#define A_SM   37888

#define CE 0.052058774f             // 768^-0.5 * log2(e)

__global__ __launch_bounds__(256, 2) void k_attn7(const int* __restrict__ amask,
                                                  float* __restrict__ out) {
    extern __shared__ __align__(128) char smem[];
    const uint32_t smb = smem_u32(smem);

    const int bh = blockIdx.y, b = bh / NH, h = bh % NH;
    const int q0 = blockIdx.x * QT;
    const int tid = threadIdx.x, wid = tid >> 5, lid = tid & 31;
    const int g = lid >> 2, t4 = lid & 3;
    const int w16 = wid * 16;
    const int l7 = lid & 7;
    const int r8  = (lid & 8)  ? 8 : 0;
    const int r16 = (lid & 16) ? 8 : 0;

    const uint32_t* T16 = g_t16 + (size_t)bh * NSEQ * (HD / 2);
    const int* mb = amask + (size_t)b * NSEQ;
    float* biasf = (float*)(smem + A_OB);

    // prologue: Q fp16, KV tile 0, bias 0
#pragma unroll
    for (int it = 0; it < 4; it++) {
        int f = tid + it * 256;
        int r = f >> 3, c = f & 7;
        uint32_t dst = smb + A_Q + (uint32_t)(r * 144 + c * 16);
        asm volatile("cp.async.cg.shared.global [%0], [%1], 16;"
                     :: "r"(dst), "l"(T16 + (size_t)(q0 + r) * 32 + c * 4));
    }
#pragma unroll
    for (int it = 0; it < 2; it++) {
        int f = tid + it * 256;
        int r = f >> 3, c = f & 7;
        uint32_t dst = smb + A_KV + (uint32_t)(r * 144 + c * 16);
        asm volatile("cp.async.cg.shared.global [%0], [%1], 16;"
                     :: "r"(dst), "l"(T16 + (size_t)r * 32 + c * 4));
    }
    asm volatile("cp.async.commit_group;" ::: "memory");
    if (tid < 64) biasf[tid] = (mb[tid] == 0) ? -3000.f : 0.f;

    float rs0 = 0.f, rs1 = 0.f;
    float oacc[4][2][4];
#pragma unroll
    for (int me = 0; me < 4; me++)
#pragma unroll
        for (int n = 0; n < 2; n++)
#pragma unroll
            for (int r = 0; r < 4; r++) oacc[me][n][r] = 0.f;

    const uint32_t qro = (uint32_t)((w16 + l7 + r8) * 144 + r16 * 2);
    const uint32_t kro = (uint32_t)((l7 + r16) * 144 + r8 * 2);

#pragma unroll 1
    for (int i = 0; i < NIT; i++) {
        asm volatile("cp.async.wait_group 0;" ::: "memory");
        __syncthreads();

        if (i + 1 < NIT) {
            int j0 = (i + 1) * KT;
            uint32_t kst = A_KV + ((i + 1) & 1) * A_KVST;
#pragma unroll
            for (int it = 0; it < 2; it++) {
                int f = tid + it * 256;
                int r = f >> 3, c = f & 7;
                uint32_t dst = smb + kst + (uint32_t)(r * 144 + c * 16);
                asm volatile("cp.async.cg.shared.global [%0], [%1], 16;"
                             :: "r"(dst), "l"(T16 + (size_t)(j0 + r) * 32 + c * 4));
            }
            asm volatile("cp.async.commit_group;" ::: "memory");
            if (tid < 64)
                biasf[((i + 1) & 1) * 64 + tid] =
                    (mb[j0 + tid] == 0) ? -3000.f : 0.f;
        }

        const uint32_t kvb = smb + A_KV + (i & 1) * A_KVST;

        // ---- S = Q K^T (fp16): 16q x 64key ----
        float sacc[8][4];
#pragma unroll
        for (int kg = 0; kg < 8; kg++)
#pragma unroll
            for (int r = 0; r < 4; r++) sacc[kg][r] = 0.f;

#pragma unroll
        for (int kb = 0; kb < 4; kb++) {
            uint32_t qf[4];
            ldsm4(qf, smb + A_Q + qro + kb * 32);
#pragma unroll
            for (int kt = 0; kt < 4; kt++) {
                uint32_t kf[4];
                ldsm4(kf, kvb + (uint32_t)(kt * 16 * 144) + kro + kb * 32);
                mma16h(sacc[kt * 2],     qf, kf);
                mma16h(sacc[kt * 2 + 1], qf, kf + 2);
            }
        }

        // ---- exp via MUFU ex2 -> packed fp16 PV B-frags ----
        uint32_t u01[8], u23[8];
        const float* bi = biasf + (i & 1) * 64;
#pragma unroll
        for (int kg = 0; kg < 8; kg++) {
            float bx = bi[kg * 8 + 2 * t4];
            float by = bi[kg * 8 + 2 * t4 + 1];
            float* c = sacc[kg];
            float p0 = ex2(fmaf(c[0], CE, bx));
            float p1 = ex2(fmaf(c[1], CE, by));
            float p2 = ex2(fmaf(c[2], CE, bx));
            float p3 = ex2(fmaf(c[3], CE, by));
            rs0 += p0 + p1;
            rs1 += p2 + p3;
            u01[kg] = packf16(p0, p1);
            u23[kg] = packf16(p2, p3);
        }

        // ---- O^T += V^T P^T (V tile == KV tile) ----
#pragma unroll
        for (int kt = 0; kt < 4; kt++) {
            uint32_t b0[2] = { u01[kt * 2], u01[kt * 2 + 1] };
            uint32_t b1[2] = { u23[kt * 2], u23[kt * 2 + 1] };
#pragma unroll
            for (int me = 0; me < 4; me++) {
                uint32_t ah[4];
                ldsm4t(ah, kvb + (uint32_t)((kt * 16 + l7 + r16) * 144
                                            + (me * 16 + r8) * 2));
                mma16h(oacc[me][0], ah, b0);
                mma16h(oacc[me][1], ah, b1);
            }
        }
    }

    // ---- epilogue ----
    rs0 += __shfl_xor_sync(0xffffffffu, rs0, 1);
    rs0 += __shfl_xor_sync(0xffffffffu, rs0, 2);
    rs1 += __shfl_xor_sync(0xffffffffu, rs1, 1);
    rs1 += __shfl_xor_sync(0xffffffffu, rs1, 2);
    float* lred = (float*)(smem + A_OL);
    if (t4 == 0) {
        lred[w16 + g] = rs0;
        lred[w16 + 8 + g] = rs1;
    }
    __syncthreads();

    const int qa = w16 + 2 * t4;
    const float inv0 = 1.f / lred[qa];
    const float inv1 = 1.f / lred[qa + 1];
    const float inv2 = 1.f / lred[qa + 8];
    const float inv3 = 1.f / lred[qa + 9];
    float* ob = out + ((size_t)b * NSEQ + q0 + qa) * (NH * HD) + h * HD;
#pragma unroll
    for (int me = 0; me < 4; me++) {
        int e0 = me * 16 + g;
        ob[e0]                   = oacc[me][0][0] * inv0;
        ob[NH * HD + e0]         = oacc[me][0][1] * inv1;
        ob[e0 + 8]               = oacc[me][0][2] * inv0;
        ob[NH * HD + e0 + 8]     = oacc[me][0][3] * inv1;
        ob[8 * NH * HD + e0]     = oacc[me][1][0] * inv2;
        ob[9 * NH * HD + e0]     = oacc[me][1][1] * inv3;
        ob[8 * NH * HD + e0 + 8] = oacc[me][1][2] * inv2;
        ob[9 * NH * HD + e0 + 8] = oacc[me][1][3] * inv3;
    }
}

// ---------------------------------------------------------------------------
extern "C" void kernel_launch(void* const* d_in, const int* in_sizes, int n_in,
                              void* d_out, int out_size) {
    const float* hidden = (const float*)d_in[0];
    const int*   amask  = (const int*)d_in[1];
    const float* Wt     = (const float*)d_in[2];
    const float* Wa     = (const float*)d_in[3];
    float* out = (float*)d_out;

    k_pre<<<WC_BLKS + CVT_BLKS, 256>>>(hidden, Wt, Wa);

    cudaFuncSetAttribute(k_proj_mma, cudaFuncAttributeMaxDynamicSharedMemorySize,
                         PROJ_SMEM_BYTES);
    k_proj_mma<<<dim3(NSEQ / 128, NB * NH), 256, PROJ_SMEM_BYTES>>>(0);

    cudaFuncSetAttribute(k_attn7, cudaFuncAttributeMaxDynamicSharedMemorySize,
                         A_SM);
    k_attn7<<<dim3(NSEQ / QT, NB * NH), 256, A_SM>>>(amask, out);
}